// round 12
// baseline (speedup 1.0000x reference)
#include <cuda_runtime.h>
#include <cuda_bf16.h>
#include <math.h>
#include <stdint.h>

#define NTOK 2048
#define BATCH 2
#define DIMV 768
#define NHEAD 12
#define HDIM 64
#define KNN 32
#define DFF 3072
#define MROWS 4096
#define QMAX 16256.0f
#define PSTRIDE 8192

#define ARENA_BYTES 186000000ull
__device__ __align__(128) char g_arena[ARENA_BYTES];
__device__ int   g_idx[MROWS * KNN];
__device__ float g_dist[MROWS * KNN];

// ---------------------------------------------------------------------------
__device__ __forceinline__ float gelu_f(float v) {
    return 0.5f * v * (1.f + erff(v * 0.70710678118654752f));
}
__device__ __forceinline__ void quant_limbs(float v, float inv_s, char& q1c, char& q0c) {
    int q = __float2int_rn(v * inv_s);
    q = max(-16256, min(16256, q));
    int q1 = (q + 64) >> 7;
    int q0 = q - (q1 << 7);
    q1c = (char)q1; q0c = (char)q0;
}

// ---------------------------------------------------------------------------
// merged per-column absmax for ALL weights (8 K-chunks) + qkv bias concat
__global__ void __launch_bounds__(256) wpmax_all_kernel(
    const float* __restrict__ Wq, const float* __restrict__ Wk, const float* __restrict__ Wv,
    const float* __restrict__ Wo, const float* __restrict__ W1, const float* __restrict__ W2,
    const float* __restrict__ bq, const float* __restrict__ bk, const float* __restrict__ bv,
    float* __restrict__ partial, float* __restrict__ bqkv)
{
    int j = blockIdx.x * 256 + threadIdx.x;          // 0..6911
    int y = blockIdx.y;
    const float* W; int c, K, Nc;
    if (j < 2304) {
        int w = j / 768; c = j - w * 768;
        W = (w == 0) ? Wq : (w == 1) ? Wk : Wv; K = 768; Nc = 768;
        if (y == 0) bqkv[j] = ((w == 0) ? bq : (w == 1) ? bk : bv)[c];
    } else {
        int r = j - 2304;
        if (r < 768)      { W = Wo; c = r;        K = 768;  Nc = 768;  }
        else if (r < 3840){ W = W1; c = r - 768;  K = 768;  Nc = 3072; }
        else              { W = W2; c = r - 3840; K = 3072; Nc = 768;  }
    }
    int chunk = K >> 3, k0 = y * chunk;
    float mx = 0.f;
    for (int k = k0; k < k0 + chunk; k++) mx = fmaxf(mx, fabsf(W[(size_t)k * Nc + c]));
    partial[y * PSTRIDE + j] = mx;
}

// ---------------------------------------------------------------------------
// qkv weight transpose+quant (256 threads, 32x32 tiles)
__global__ void __launch_bounds__(256) wquantT3_kernel(
    const float* __restrict__ Wq, const float* __restrict__ Wk, const float* __restrict__ Wv,
    const float* __restrict__ partial, float* __restrict__ sB,
    char* __restrict__ o1, char* __restrict__ o0)
{
    __shared__ char s1[32][33], s0[32][33];
    int z = blockIdx.z;
    const float* W = (z == 0) ? Wq : (z == 1) ? Wk : Wv;
    int n0 = blockIdx.x * 32, k0 = blockIdx.y * 32, rowOff = z * 768;
    int tid = threadIdx.x, tx = tid & 31, tyg = tid >> 5;
    int n = n0 + tx;
    float mx = 0.f;
#pragma unroll
    for (int j = 0; j < 8; j++) mx = fmaxf(mx, partial[j * PSTRIDE + rowOff + n]);
    mx = fmaxf(mx, 1e-20f);
    float inv = QMAX / mx;
    if (k0 == 0 && tyg == 0) sB[rowOff + n] = mx / QMAX;
#pragma unroll
    for (int j = 0; j < 4; j++) {
        int kl = tyg * 4 + j;
        float v = W[(size_t)(k0 + kl) * 768 + n];
        quant_limbs(v, inv, s1[kl][tx], s0[kl][tx]);
    }
    __syncthreads();
#pragma unroll
    for (int j = 0; j < 4; j++) {
        int nl = tyg * 4 + j;
        size_t oidx = (size_t)(rowOff + n0 + nl) * 768 + k0 + tx;
        o1[oidx] = s1[tx][nl];
        o0[oidx] = s0[tx][nl];
    }
}

// ---------------------------------------------------------------------------
// weight transpose+quant: 512 threads, 32 cols x 64 k tile (static smem)
__global__ void __launch_bounds__(512) wq64_kernel(
    const float* __restrict__ W, const float* __restrict__ partial, int pcolOff,
    float* __restrict__ sBout, char* __restrict__ o1, char* __restrict__ o0,
    int Nc, int Kd)
{
    __shared__ char s1[64 * 33], s0[64 * 33];
    int n0 = blockIdx.x * 32, k0 = blockIdx.y * 64;
    int tid = threadIdx.x;
    int tx = tid & 31, ky = tid >> 5;  // ky 0..15
    int n = n0 + tx;
    float mx = 0.f;
#pragma unroll
    for (int j = 0; j < 8; j++) mx = fmaxf(mx, partial[j * PSTRIDE + pcolOff + n]);
    mx = fmaxf(mx, 1e-20f);
    float inv = QMAX / mx;
    if (k0 == 0 && ky == 0) sBout[n] = mx / QMAX;
#pragma unroll
    for (int j = 0; j < 4; j++) {
        int kl = ky * 4 + j;
        float v = W[(size_t)(k0 + kl) * Nc + n];
        char q1, q0;
        quant_limbs(v, inv, q1, q0);
        s1[kl * 33 + tx] = q1;
        s0[kl * 33 + tx] = q0;
    }
    __syncthreads();
    int nl = tid >> 4, kq = (tid & 15) * 4;
    size_t ob = (size_t)(n0 + nl) * Kd + k0 + kq;
    uchar4 a, bqt;
    a.x = s1[(kq + 0) * 33 + nl]; a.y = s1[(kq + 1) * 33 + nl];
    a.z = s1[(kq + 2) * 33 + nl]; a.w = s1[(kq + 3) * 33 + nl];
    bqt.x = s0[(kq + 0) * 33 + nl]; bqt.y = s0[(kq + 1) * 33 + nl];
    bqt.z = s0[(kq + 2) * 33 + nl]; bqt.w = s0[(kq + 3) * 33 + nl];
    *(uchar4*)(o1 + ob) = a;
    *(uchar4*)(o0 + ob) = bqt;
}

// ---------------------------------------------------------------------------
// LayerNorm (+time emb) -> int8 limb planes + per-row scale
__global__ void __launch_bounds__(384) ln_quant_kernel(const float* __restrict__ x,
    const float* __restrict__ g, const float* __restrict__ be,
    const float* __restrict__ temb, char* __restrict__ o1, char* __restrict__ o0,
    float* __restrict__ sA)
{
    __shared__ float sb[13];
    int row = blockIdx.x, tid = threadIdx.x;
    int lane = tid & 31, w = tid >> 5;
    float2 xv = *(const float2*)(x + (size_t)row * DIMV + 2 * tid);
    float s = xv.x + xv.y;
#pragma unroll
    for (int o = 16; o; o >>= 1) s += __shfl_xor_sync(0xffffffffu, s, o);
    if (lane == 0) sb[w] = s;
    __syncthreads();
    if (w == 0) {
        float r = (lane < 12) ? sb[lane] : 0.f;
#pragma unroll
        for (int o = 16; o; o >>= 1) r += __shfl_xor_sync(0xffffffffu, r, o);
        if (lane == 0) sb[12] = r;
    }
    __syncthreads();
    float mu = sb[12] * (1.0f / DIMV);
    float dx = xv.x - mu, dy = xv.y - mu;
    float vs = dx * dx + dy * dy;
    __syncthreads();
#pragma unroll
    for (int o = 16; o; o >>= 1) vs += __shfl_xor_sync(0xffffffffu, vs, o);
    if (lane == 0) sb[w] = vs;
    __syncthreads();
    if (w == 0) {
        float r = (lane < 12) ? sb[lane] : 0.f;
#pragma unroll
        for (int o = 16; o; o >>= 1) r += __shfl_xor_sync(0xffffffffu, r, o);
        if (lane == 0) sb[12] = r;
    }
    __syncthreads();
    float inv = rsqrtf(sb[12] * (1.0f / DIMV) + 1e-5f);
    int b = row >> 11;
    int i0 = 2 * tid;
    float v0 = dx * inv * g[i0] + be[i0];
    float v1 = dy * inv * g[i0 + 1] + be[i0 + 1];
    if (temb) { v0 += temb[b * DIMV + i0]; v1 += temb[b * DIMV + i0 + 1]; }
    float mx = fmaxf(fabsf(v0), fabsf(v1));
    __syncthreads();
#pragma unroll
    for (int o = 16; o; o >>= 1) mx = fmaxf(mx, __shfl_xor_sync(0xffffffffu, mx, o));
    if (lane == 0) sb[w] = mx;
    __syncthreads();
    if (w == 0) {
        float r = (lane < 12) ? sb[lane] : 0.f;
#pragma unroll
        for (int o = 16; o; o >>= 1) r = fmaxf(r, __shfl_xor_sync(0xffffffffu, r, o));
        if (lane == 0) sb[12] = r;
    }
    __syncthreads();
    float rmax = fmaxf(sb[12], 1e-20f);
    float invs = QMAX / rmax;
    char a1, a0, b1, b0;
    quant_limbs(v0, invs, a1, a0);
    quant_limbs(v1, invs, b1, b0);
    size_t oi = (size_t)row * DIMV + i0;
    *(char2*)(o1 + oi) = make_char2(a1, b1);
    *(char2*)(o0 + oi) = make_char2(a0, b0);
    if (tid == 0) sA[row] = rmax / QMAX;
}

// ---------------------------------------------------------------------------
// int8 limb GEMM (3-pass). Block 128x128, 512 thr, BK=64, 4-stage cp.async.
// ---------------------------------------------------------------------------
#define O_A1 0
#define O_A0 8192
#define O_B1 16384
#define O_B0 24576
#define STG_BYTES 32768
#define GEMM_SMEM (4 * STG_BYTES)   // 128KB

__device__ __forceinline__ void cp16s(uint32_t sdst, const void* src) {
    asm volatile("cp.async.cg.shared.global [%0], [%1], 16;" :: "r"(sdst), "l"(src));
}
#define LDSM4(r, addr)                                                        \
    asm volatile("ldmatrix.sync.aligned.m8n8.x4.shared.b16 {%0,%1,%2,%3}, [%4];" \
        : "=r"((r)[0]), "=r"((r)[1]), "=r"((r)[2]), "=r"((r)[3]) : "r"(addr))
#define MMA_S8(d, a, b0, b1)                                                  \
    asm volatile(                                                             \
        "mma.sync.aligned.m16n8k32.row.col.s32.s8.s8.s32 "                    \
        "{%0,%1,%2,%3},{%4,%5,%6,%7},{%8,%9},{%0,%1,%2,%3};"                  \
        : "+r"((d)[0]), "+r"((d)[1]), "+r"((d)[2]), "+r"((d)[3])              \
        : "r"((a)[0]), "r"((a)[1]), "r"((a)[2]), "r"((a)[3]), "r"(b0), "r"(b1))

__global__ void __launch_bounds__(512, 1) s8_gemm_kernel(
    const char* __restrict__ A1, const char* __restrict__ A0,
    const char* __restrict__ B1, const char* __restrict__ B0,
    const float* __restrict__ sA, const float* __restrict__ sB,
    const float* __restrict__ bias, const float* __restrict__ res,
    float* __restrict__ Cf, int Nc, int K, int act)
{
    extern __shared__ __align__(128) char smc[];
    const int tid = threadIdx.x;
    const int warp = tid >> 5, lane = tid & 31;
    const int wm = warp & 3, wn = warp >> 2;
    const int g = lane >> 2, t = lane & 3;
    const int bm = blockIdx.y * 128, bn = blockIdx.x * 128;
    const int nk = K >> 6;

    uint32_t sbase;
    asm("{ .reg .u64 tt; cvta.to.shared.u64 tt, %1; cvt.u32.u64 %0, tt; }"
        : "=r"(sbase) : "l"(smc));

    const int arl = lane & 15, aqb = lane >> 4;
    const int arsw = (arl >> 1) & 3;
    uint32_t aoff[2], aq[2];
#pragma unroll
    for (int mi = 0; mi < 2; mi++)
        aoff[mi] = (uint32_t)(wm * 32 + mi * 16 + arl) * 64u;
#pragma unroll
    for (int ks = 0; ks < 2; ks++)
        aq[ks] = (uint32_t)(((2 * ks + aqb) ^ arsw) << 4);
    const int nrl = (lane & 7) + ((lane >> 4) << 3);
    const int bqb = (lane >> 3) & 1;
    const int brsw = (nrl >> 1) & 3;
    uint32_t boff[2], bq[2];
#pragma unroll
    for (int ni = 0; ni < 2; ni++)
        boff[ni] = (uint32_t)(wn * 32 + ni * 16 + nrl) * 64u;
#pragma unroll
    for (int ks = 0; ks < 2; ks++)
        bq[ks] = (uint32_t)(((2 * ks + bqb) ^ brsw) << 4);

    int hh[2][2][2][4], cx[2][2][2][4];
#pragma unroll
    for (int mi = 0; mi < 2; mi++)
#pragma unroll
        for (int ni = 0; ni < 2; ni++)
#pragma unroll
            for (int pr = 0; pr < 2; pr++)
#pragma unroll
                for (int e = 0; e < 4; e++) { hh[mi][ni][pr][e] = 0; cx[mi][ni][pr][e] = 0; }

    auto load_stage = [&](int buf, int it) {
        if (it < nk) {
            uint32_t st = sbase + buf * STG_BYTES;
            int kb = it * 64;
            int m = tid >> 2, q = tid & 3;
            uint32_t woff = (uint32_t)(m * 64 + ((q ^ ((m >> 1) & 3)) << 4));
            size_t ga = (size_t)(bm + m) * K + kb + q * 16;
            cp16s(st + O_A1 + woff, A1 + ga);
            cp16s(st + O_A0 + woff, A0 + ga);
            size_t gb = (size_t)(bn + m) * K + kb + q * 16;
            cp16s(st + O_B1 + woff, B1 + gb);
            cp16s(st + O_B0 + woff, B0 + gb);
        }
        asm volatile("cp.async.commit_group;");
    };

    load_stage(0, 0);
    load_stage(1, 1);
    load_stage(2, 2);

    for (int it = 0; it < nk; it++) {
        asm volatile("cp.async.wait_group 2;");
        __syncthreads();
        load_stage((it + 3) & 3, it + 3);

        uint32_t st = sbase + (it & 3) * STG_BYTES;
#pragma unroll
        for (int ks = 0; ks < 2; ks++) {
            uint32_t fA1[2][4], fA0[2][4], fB1[2][4], fB0[2][4];
#pragma unroll
            for (int mi = 0; mi < 2; mi++)
                LDSM4(fA1[mi], st + O_A1 + aoff[mi] + aq[ks]);
#pragma unroll
            for (int ni = 0; ni < 2; ni++)
                LDSM4(fB1[ni], st + O_B1 + boff[ni] + bq[ks]);
#pragma unroll
            for (int mi = 0; mi < 2; mi++)
#pragma unroll
                for (int ni = 0; ni < 2; ni++)
#pragma unroll
                    for (int pr = 0; pr < 2; pr++)
                        MMA_S8(hh[mi][ni][pr], fA1[mi], fB1[ni][2 * pr], fB1[ni][2 * pr + 1]);
#pragma unroll
            for (int ni = 0; ni < 2; ni++)
                LDSM4(fB0[ni], st + O_B0 + boff[ni] + bq[ks]);
#pragma unroll
            for (int mi = 0; mi < 2; mi++)
#pragma unroll
                for (int ni = 0; ni < 2; ni++)
#pragma unroll
                    for (int pr = 0; pr < 2; pr++)
                        MMA_S8(cx[mi][ni][pr], fA1[mi], fB0[ni][2 * pr], fB0[ni][2 * pr + 1]);
#pragma unroll
            for (int mi = 0; mi < 2; mi++)
                LDSM4(fA0[mi], st + O_A0 + aoff[mi] + aq[ks]);
#pragma unroll
            for (int mi = 0; mi < 2; mi++)
#pragma unroll
                for (int ni = 0; ni < 2; ni++)
#pragma unroll
                    for (int pr = 0; pr < 2; pr++)
                        MMA_S8(cx[mi][ni][pr], fA0[mi], fB1[ni][2 * pr], fB1[ni][2 * pr + 1]);
        }
    }

#pragma unroll
    for (int mi = 0; mi < 2; mi++) {
#pragma unroll
        for (int ni = 0; ni < 2; ni++) {
#pragma unroll
            for (int pr = 0; pr < 2; pr++) {
                int col = bn + wn * 32 + ni * 16 + pr * 8 + 2 * t;
                float2 sb2 = *(const float2*)(sB + col);
                float2 bb = *(const float2*)(bias + col);
#pragma unroll
                for (int hf = 0; hf < 2; hf++) {
                    int r = bm + wm * 32 + mi * 16 + g + hf * 8;
                    float sa = sA[r];
                    float vx = sa * sb2.x * (16384.f * (float)hh[mi][ni][pr][2 * hf]
                              + 128.f * (float)cx[mi][ni][pr][2 * hf]) + bb.x;
                    float vy = sa * sb2.y * (16384.f * (float)hh[mi][ni][pr][2 * hf + 1]
                              + 128.f * (float)cx[mi][ni][pr][2 * hf + 1]) + bb.y;
                    if (act) { vx = gelu_f(vx); vy = gelu_f(vy); }
                    if (res) {
                        const float2 rr = *(const float2*)(res + (size_t)r * Nc + col);
                        vx += rr.x; vy += rr.y;
                    }
                    float2 o; o.x = vx; o.y = vy;
                    *(float2*)(Cf + (size_t)r * Nc + col) = o;
                }
            }
        }
    }
}

// ---------------------------------------------------------------------------
// topk: 8 rows/block, 512 threads phase 1, 8 warps phase 2 (128KB smem)
// ---------------------------------------------------------------------------
#define TOPK_SMEM 131072
__device__ __forceinline__ void ce64(unsigned long long& a, unsigned long long& b) {
    unsigned long long lo = min(a, b), hi = max(a, b);
    a = lo; b = hi;
}

__global__ void __launch_bounds__(512, 1) topk8_kernel(const float* __restrict__ pos,
    const float* __restrict__ cptr, int* __restrict__ idxo, float* __restrict__ disto)
{
    extern __shared__ __align__(128) char dsm[];
    unsigned long long* skv = (unsigned long long*)dsm;   // [8][2048]
    int tid = threadIdx.x;
    int base = blockIdx.x * 8;
    int b = base >> 11;
    float c = cptr[0];
    float inv_sqc = rsqrtf(c);
    const float* pb = pos + (size_t)b * NTOK * 2;
    int lt = tid & 255, half = tid >> 8;

#pragma unroll
    for (int p2 = 0; p2 < 4; p2++) {
        int rowSlot = p2 * 2 + half;
        int i = (base + rowSlot) & (NTOK - 1);
        float yx = pb[i * 2], yy = pb[i * 2 + 1];
        float denY = 1.f - c * (yx * yx + yy * yy);
        unsigned long long k[8];
#pragma unroll
        for (int u = 0; u < 8; u++) {
            int j = lt + u * 256;
            float2 pj = *(const float2*)(pb + j * 2);
            float dx = pj.x - yx, dy = pj.y - yy;
            float num = 2.f * c * (dx * dx + dy * dy);
            float den = (1.f - c * (pj.x * pj.x + pj.y * pj.y)) * denY;
            float v = fmaxf(1.f + num / (den + 1e-8f), 1.f);
            k[u] = ((unsigned long long)__float_as_uint(v) << 32) | (unsigned)j;
        }
        ce64(k[0],k[1]); ce64(k[2],k[3]); ce64(k[4],k[5]); ce64(k[6],k[7]);
        ce64(k[0],k[2]); ce64(k[1],k[3]); ce64(k[4],k[6]); ce64(k[5],k[7]);
        ce64(k[1],k[2]); ce64(k[5],k[6]);
        ce64(k[0],k[4]); ce64(k[1],k[5]); ce64(k[2],k[6]); ce64(k[3],k[7]);
        ce64(k[2],k[4]); ce64(k[3],k[5]);
        ce64(k[1],k[2]); ce64(k[3],k[4]); ce64(k[5],k[6]);
#pragma unroll
        for (int u = 0; u < 8; u++) skv[rowSlot * 2048 + lt * 8 + u] = k[u];
    }
    __syncthreads();
    if (tid >= 256) return;

    int w = tid >> 5, lane = tid & 31;
    unsigned long long* rs = skv + w * 2048;
    unsigned long long head[8];
    int ptr[8];
#pragma unroll
    for (int h = 0; h < 8; h++) { head[h] = rs[(lane * 8 + h) * 8]; ptr[h] = 0; }
    unsigned long long lmin = head[0]; int lh = 0;
#pragma unroll
    for (int h = 1; h < 8; h++)
        if (head[h] < lmin) { lmin = head[h]; lh = h; }

    unsigned long long mykey = 0xFFFFFFFFFFFFFFFFull;
    for (int sel = 0; sel < KNN; sel++) {
        unsigned long long bk = lmin; int bl = lane;
#pragma unroll
        for (int o = 16; o; o >>= 1) {
            unsigned long long ok = __shfl_xor_sync(0xffffffffu, bk, o);
            int ol = __shfl_xor_sync(0xffffffffu, bl, o);
            if (ok < bk) { bk = ok; bl = ol; }
        }
        if (lane == sel) mykey = bk;
        if (lane == bl) {
            int pp = ++ptr[lh];
            head[lh] = (pp < 8) ? rs[(lane * 8 + lh) * 8 + pp] : 0xFFFFFFFFFFFFFFFFull;
            lmin = head[0]; lh = 0;
#pragma unroll
            for (int h = 1; h < 8; h++)
                if (head[h] < lmin) { lmin = head[h]; lh = h; }
        }
    }
    int row = base + w;
    float v = __uint_as_float((unsigned)(mykey >> 32));
    idxo[(size_t)row * KNN + lane] = (int)(unsigned)(mykey & 0xFFFFFFFFull);
    disto[(size_t)row * KNN + lane] = acoshf(v) * inv_sqc;
}

// ---------------------------------------------------------------------------
// K/V fp32 -> s16 with per-row scales
__global__ void __launch_bounds__(384) kv16_kernel(const float* __restrict__ qkv,
    short* __restrict__ kv16, float* __restrict__ scK, float* __restrict__ scV)
{
    __shared__ float sb[32];
    int row = blockIdx.x, tid = threadIdx.x;
    int lane = tid & 31, w = tid >> 5;
    const float* kr = qkv + (size_t)row * 2304 + 768;
    float2 kv = *(const float2*)(kr + 2 * tid);
    float2 vv = *(const float2*)(kr + 768 + 2 * tid);
    float mk = fmaxf(fabsf(kv.x), fabsf(kv.y));
    float mv = fmaxf(fabsf(vv.x), fabsf(vv.y));
#pragma unroll
    for (int o = 16; o; o >>= 1) {
        mk = fmaxf(mk, __shfl_xor_sync(0xffffffffu, mk, o));
        mv = fmaxf(mv, __shfl_xor_sync(0xffffffffu, mv, o));
    }
    if (lane == 0) { sb[w] = mk; sb[16 + w] = mv; }
    __syncthreads();
    if (w == 0) {
        float rk = (lane < 12) ? sb[lane] : 0.f;
        float rv = (lane < 12) ? sb[16 + lane] : 0.f;
#pragma unroll
        for (int o = 16; o; o >>= 1) {
            rk = fmaxf(rk, __shfl_xor_sync(0xffffffffu, rk, o));
            rv = fmaxf(rv, __shfl_xor_sync(0xffffffffu, rv, o));
        }
        if (lane == 0) { sb[12] = rk; sb[28] = rv; }
    }
    __syncthreads();
    float sk = fmaxf(sb[12], 1e-20f), sv = fmaxf(sb[28], 1e-20f);
    float ik = 32767.f / sk, iv = 32767.f / sv;
    short2 ko, vo;
    ko.x = (short)__float2int_rn(kv.x * ik); ko.y = (short)__float2int_rn(kv.y * ik);
    vo.x = (short)__float2int_rn(vv.x * iv); vo.y = (short)__float2int_rn(vv.y * iv);
    *(short2*)(kv16 + (size_t)row * 1536 + 2 * tid) = ko;
    *(short2*)(kv16 + (size_t)row * 1536 + 768 + 2 * tid) = vo;
    if (tid == 0) { scK[row] = sk / 32767.f; scV[row] = sv / 32767.f; }
}

// ---------------------------------------------------------------------------
// kNN attention over s16 K/V; int8-limb output + row scale
__global__ void __launch_bounds__(384) attn_quant_kernel(const float* __restrict__ qkv,
    const short* __restrict__ kv16, const float* __restrict__ scK,
    const float* __restrict__ scV, const int* __restrict__ idx,
    const float* __restrict__ dist, const float* __restrict__ log_tau,
    char* __restrict__ o1, char* __restrict__ o0, float* __restrict__ sA)
{
    __shared__ int sidx[KNN];
    __shared__ float sgeo[KNN], sKn[KNN], sVn[KNN];
    __shared__ float smax[13];
    int row = blockIdx.x;
    int lane = threadIdx.x & 31, h = threadIdx.x >> 5;
    int b = row >> 11;
    float invtau = 1.f / (expf(log_tau[0]) + 1e-8f);
    if (threadIdx.x < KNN) {
        int id = idx[(size_t)row * KNN + threadIdx.x];
        sidx[threadIdx.x] = id;
        sgeo[threadIdx.x] = -dist[(size_t)row * KNN + threadIdx.x] * invtau;
        sKn[threadIdx.x] = scK[b * NTOK + id] * 0.125f;
        sVn[threadIdx.x] = scV[b * NTOK + id];
    }
    __syncthreads();
    const float* qp = qkv + (size_t)row * 2304 + h * HDIM;
    float q0 = qp[2 * lane], q1 = qp[2 * lane + 1];
    const short* kvb = kv16 + (size_t)b * NTOK * 1536;
    float myscore = 0.f;
#pragma unroll
    for (int j0 = 0; j0 < KNN; j0 += 8) {
        float ka[8], kc[8];
#pragma unroll
        for (int u = 0; u < 8; u++) {
            short2 ks = *(const short2*)(kvb + (size_t)sidx[j0 + u] * 1536 + h * HDIM + 2 * lane);
            ka[u] = (float)ks.x; kc[u] = (float)ks.y;
        }
#pragma unroll
        for (int u = 0; u < 8; u++) {
            float p = q0 * ka[u] + q1 * kc[u];
#pragma unroll
            for (int o = 16; o; o >>= 1) p += __shfl_xor_sync(0xffffffffu, p, o);
            if (lane == j0 + u) myscore = p * sKn[j0 + u] + sgeo[j0 + u];
        }
    }
    float m = myscore;
#pragma unroll
    for (int o = 16; o; o >>= 1) m = fmaxf(m, __shfl_xor_sync(0xffffffffu, m, o));
    float e = expf(myscore - m);
    float s = e;
#pragma unroll
    for (int o = 16; o; o >>= 1) s += __shfl_xor_sync(0xffffffffu, s, o);
    float p = e / s;
    float v0 = 0.f, v1 = 0.f;
#pragma unroll
    for (int j0 = 0; j0 < KNN; j0 += 8) {
        float va[8], vc[8];
#pragma unroll
        for (int u = 0; u < 8; u++) {
            short2 vs = *(const short2*)(kvb + (size_t)sidx[j0 + u] * 1536 + 768 + h * HDIM + 2 * lane);
            va[u] = (float)vs.x; vc[u] = (float)vs.y;
        }
#pragma unroll
        for (int u = 0; u < 8; u++) {
            float pj = __shfl_sync(0xffffffffu, p, j0 + u) * sVn[j0 + u];
            v0 += pj * va[u]; v1 += pj * vc[u];
        }
    }
    float mx = fmaxf(fabsf(v0), fabsf(v1));
#pragma unroll
    for (int o = 16; o; o >>= 1) mx = fmaxf(mx, __shfl_xor_sync(0xffffffffu, mx, o));
    if (lane == 0) smax[h] = mx;
    __syncthreads();
    if (h == 0) {
        float r = (lane < 12) ? smax[lane] : 0.f;
#pragma unroll
        for (int o = 16; o; o >>= 1) r = fmaxf(r, __shfl_xor_sync(0xffffffffu, r, o));
        if (lane == 0) smax[12] = r;
    }
    __syncthreads();
    float rmax = fmaxf(smax[12], 1e-20f);
    float inv = QMAX / rmax;
    char a1, a0, b1c, b0c;
    quant_limbs(v0, inv, a1, a0);
    quant_limbs(v1, inv, b1c, b0c);
    size_t oi = (size_t)row * DIMV + h * HDIM + 2 * lane;
    *(char2*)(o1 + oi) = make_char2(a1, b1c);
    *(char2*)(o0 + oi) = make_char2(a0, b0c);
    if (threadIdx.x == 0) sA[row] = rmax / QMAX;
}

// ---------------------------------------------------------------------------
// ffn row quant
__global__ void __launch_bounds__(256) ffn_quant_kernel(const float* __restrict__ f,
    char* __restrict__ o1, char* __restrict__ o0, float* __restrict__ sA)
{
    __shared__ float sb[9];
    int row = blockIdx.x, tid = threadIdx.x;
    int lane = tid & 31, w = tid >> 5;
    const float4* base = (const float4*)(f + (size_t)row * DFF);
    float mx = 0.f;
#pragma unroll
    for (int i = 0; i < 3; i++) {
        float4 v = base[tid + i * 256];
        mx = fmaxf(mx, fmaxf(fmaxf(fabsf(v.x), fabsf(v.y)), fmaxf(fabsf(v.z), fabsf(v.w))));
    }
#pragma unroll
    for (int o = 16; o; o >>= 1) mx = fmaxf(mx, __shfl_xor_sync(0xffffffffu, mx, o));
    if (lane == 0) sb[w] = mx;
    __syncthreads();
    if (w == 0) {
        float r = (lane < 8) ? sb[lane] : 0.f;
#pragma unroll
        for (int o = 4; o; o >>= 1) r = fmaxf(r, __shfl_xor_sync(0xffffffffu, r, o));
        if (lane == 0) sb[8] = r;
    }
    __syncthreads();
    float rmax = fmaxf(sb[8], 1e-20f);
    float inv = QMAX / rmax;
    uint32_t* p1 = (uint32_t*)(o1 + (size_t)row * DFF);
    uint32_t* p0 = (uint32_t*)(o0 + (size_t)row * DFF);
#pragma unroll
    for (int i = 0; i < 3; i++) {
        float4 v = base[tid + i * 256];
        char a1, a0, b1, b0, c1, c0, d1, d0;
        quant_limbs(v.x, inv, a1, a0);
        quant_limbs(v.y, inv, b1, b0);
        quant_limbs(v.z, inv, c1, c0);
        quant_limbs(v.w, inv, d1, d0);
        p1[tid + i * 256] = (uint32_t)(uint8_t)a1 | ((uint32_t)(uint8_t)b1 << 8)
                          | ((uint32_t)(uint8_t)c1 << 16) | ((uint32_t)(uint8_t)d1 << 24);
        p0[tid + i * 256] = (uint32_t)(uint8_t)a0 | ((uint32_t)(uint8_t)b0 << 8)
                          | ((uint32_t)(uint8_t)c0 << 16) | ((uint32_t)(uint8_t)d0 << 24);
    }
    if (tid == 0) sA[row] = rmax / QMAX;
}

// ---------------------------------------------------------------------------
extern "C" void kernel_launch(void* const* d_in, const int* in_sizes, int n_in,
                              void* d_out, int out_size)
{
    const float* x    = (const float*)d_in[0];
    const float* pos  = (const float*)d_in[1];
    const float* c    = (const float*)d_in[2];
    const float* temb = (const float*)d_in[3];
    const float* Wq = (const float*)d_in[4],  *bq = (const float*)d_in[5];
    const float* Wk = (const float*)d_in[6],  *bk = (const float*)d_in[7];
    const float* Wv = (const float*)d_in[8],  *bv = (const float*)d_in[9];
    const float* Wo = (const float*)d_in[10], *bo = (const float*)d_in[11];
    const float* W1 = (const float*)d_in[12], *b1 = (const float*)d_in[13];
    const float* W2 = (const float*)d_in[14], *b2 = (const float*)d_in[15];
    const float* g1 = (const float*)d_in[16], *be1 = (const float*)d_in[17];
    const float* g2 = (const float*)d_in[18], *be2 = (const float*)d_in[19];
    const float* log_tau = (const float*)d_in[20];
    float* out = (float*)d_out;

    char* arena; cudaGetSymbolAddress((void**)&arena, g_arena);
    int* idxp;   cudaGetSymbolAddress((void**)&idxp, g_idx);
    float* distp;cudaGetSymbolAddress((void**)&distp, g_dist);

    char* p = arena;
    auto carve = [&](size_t bytes) { char* r = p; p += (bytes + 127) & ~(size_t)127; return r; };
    char* h1   = carve((size_t)MROWS * 768);
    char* h0   = carve((size_t)MROWS * 768);
    char* att1 = carve((size_t)MROWS * 768);
    char* att0 = carve((size_t)MROWS * 768);
    char* h21  = carve((size_t)MROWS * 768);
    char* h20  = carve((size_t)MROWS * 768);
    char* ffn1 = carve((size_t)MROWS * 3072);
    char* ffn0 = carve((size_t)MROWS * 3072);
    char* wqkv1 = carve((size_t)2304 * 768);
    char* wqkv0 = carve((size_t)2304 * 768);
    char* wo1  = carve((size_t)768 * 768);
    char* wo0  = carve((size_t)768 * 768);
    char* w11  = carve((size_t)3072 * 768);
    char* w10  = carve((size_t)3072 * 768);
    char* w21  = carve((size_t)768 * 3072);
    char* w20  = carve((size_t)768 * 3072);
    float* qkv   = (float*)carve((size_t)MROWS * 2304 * 4);
    float* x2    = (float*)carve((size_t)MROWS * 768 * 4);
    float* ffn_f = (float*)carve((size_t)MROWS * 3072 * 4);
    short* kv16  = (short*)carve((size_t)MROWS * 1536 * 2);
    float* partial = (float*)carve(8 * PSTRIDE * 4);
    float* sAh   = (float*)carve(MROWS * 4);
    float* sAatt = (float*)carve(MROWS * 4);
    float* sAh2  = (float*)carve(MROWS * 4);
    float* sAffn = (float*)carve(MROWS * 4);
    float* scK   = (float*)carve(MROWS * 4);
    float* scV   = (float*)carve(MROWS * 4);
    float* sBqkv = (float*)carve(2304 * 4);
    float* sBo   = (float*)carve(768 * 4);
    float* sB1   = (float*)carve(3072 * 4);
    float* sB2   = (float*)carve(768 * 4);
    float* bqkv  = (float*)carve(2304 * 4);

    cudaFuncSetAttribute(s8_gemm_kernel,
                         cudaFuncAttributeMaxDynamicSharedMemorySize, GEMM_SMEM);
    cudaFuncSetAttribute(topk8_kernel,
                         cudaFuncAttributeMaxDynamicSharedMemorySize, TOPK_SMEM);

    // 1-3, then topk8 as launch 4 (= ncu capture slot)
    ln_quant_kernel<<<MROWS, 384>>>(x, g1, be1, temb, h1, h0, sAh);
    wpmax_all_kernel<<<dim3(27, 8), 256>>>(Wq, Wk, Wv, Wo, W1, W2, bq, bk, bv,
                                           partial, bqkv);
    wquantT3_kernel<<<dim3(24, 24, 3), 256>>>(Wq, Wk, Wv, partial, sBqkv, wqkv1, wqkv0);
    topk8_kernel<<<512, 512, TOPK_SMEM>>>(pos, c, idxp, distp);

    // fused QKV GEMM
    s8_gemm_kernel<<<dim3(18, 32), 512, GEMM_SMEM>>>(h1, h0, wqkv1, wqkv0,
        sAh, sBqkv, bqkv, nullptr, qkv, 2304, 768, 0);

    kv16_kernel<<<MROWS, 384>>>(qkv, kv16, scK, scV);
    attn_quant_kernel<<<MROWS, 384>>>(qkv, kv16, scK, scV, idxp, distp, log_tau,
                                      att1, att0, sAatt);

    // remaining weight quants (overlap-friendly small kernels)
    wq64_kernel<<<dim3(24, 12), 512>>>(Wo, partial, 2304, sBo, wo1, wo0, 768, 768);
    wq64_kernel<<<dim3(96, 12), 512>>>(W1, partial, 3072, sB1, w11, w10, 3072, 768);
    wq64_kernel<<<dim3(24, 48), 512>>>(W2, partial, 6144, sB2, w21, w20, 768, 3072);

    // x2 = x + att @ Wo
    s8_gemm_kernel<<<dim3(6, 32), 512, GEMM_SMEM>>>(att1, att0, wo1, wo0,
        sAatt, sBo, bo, x, x2, 768, 768, 0);
    ln_quant_kernel<<<MROWS, 384>>>(x2, g2, be2, nullptr, h21, h20, sAh2);

    // ffn_f = gelu(h2 @ W1)
    s8_gemm_kernel<<<dim3(24, 32), 512, GEMM_SMEM>>>(h21, h20, w11, w10,
        sAh2, sB1, b1, nullptr, ffn_f, 3072, 768, 1);
    ffn_quant_kernel<<<MROWS, 256>>>(ffn_f, ffn1, ffn0, sAffn);

    // out = x2 + ffn @ W2
    s8_gemm_kernel<<<dim3(6, 32), 512, GEMM_SMEM>>>(ffn1, ffn0, w21, w20,
        sAffn, sB2, b2, x2, out, 768, 3072, 0);
}

// round 13
// speedup vs baseline: 1.0794x; 1.0794x over previous
#include <cuda_runtime.h>
#include <cuda_bf16.h>
#include <math.h>
#include <stdint.h>

#define NTOK 2048
#define BATCH 2
#define DIMV 768
#define NHEAD 12
#define HDIM 64
#define KNN 32
#define DFF 3072
#define MROWS 4096
#define QMAX 16256.0f
#define PSTRIDE 8192

#define ARENA_BYTES 172000000ull
__device__ __align__(128) char g_arena[ARENA_BYTES];
__device__ int   g_idx[MROWS * KNN];
__device__ float g_dist[MROWS * KNN];

// ---------------------------------------------------------------------------
__device__ __forceinline__ float gelu_f(float v) {
    return 0.5f * v * (1.f + erff(v * 0.70710678118654752f));
}
__device__ __forceinline__ void quant_limbs(float v, float inv_s, char& q1c, char& q0c) {
    int q = __float2int_rn(v * inv_s);
    q = max(-16256, min(16256, q));
    int q1 = (q + 64) >> 7;
    int q0 = q - (q1 << 7);
    q1c = (char)q1; q0c = (char)q0;
}

// ---------------------------------------------------------------------------
// parallel per-column absmax, 8 K-chunks; qkv variant also concats bias
__global__ void __launch_bounds__(256) wpmax_qkv_kernel(
    const float* __restrict__ Wq, const float* __restrict__ Wk, const float* __restrict__ Wv,
    const float* __restrict__ bq, const float* __restrict__ bk, const float* __restrict__ bv,
    float* __restrict__ partial, float* __restrict__ bqkv)
{
    int col = blockIdx.x * 256 + threadIdx.x;        // 0..2303
    int w = col / 768, c = col - w * 768;
    const float* W = (w == 0) ? Wq : (w == 1) ? Wk : Wv;
    int k0 = blockIdx.y * 96;
    float mx = 0.f;
#pragma unroll 8
    for (int k = k0; k < k0 + 96; k++) mx = fmaxf(mx, fabsf(W[(size_t)k * 768 + c]));
    partial[blockIdx.y * PSTRIDE + col] = mx;
    if (blockIdx.y == 0)
        bqkv[col] = ((w == 0) ? bq : (w == 1) ? bk : bv)[c];
}

__global__ void __launch_bounds__(256) wpmax_rest_kernel(
    const float* __restrict__ Wo, const float* __restrict__ W1, const float* __restrict__ W2,
    float* __restrict__ partial)
{
    int j = blockIdx.x * 256 + threadIdx.x;          // 0..4607
    const float* W; int c, K, Nc;
    if (j < 768)       { W = Wo; c = j;        K = 768;  Nc = 768;  }
    else if (j < 3840) { W = W1; c = j - 768;  K = 768;  Nc = 3072; }
    else               { W = W2; c = j - 3840; K = 3072; Nc = 768;  }
    int chunk = K >> 3;
    int k0 = blockIdx.y * chunk;
    float mx = 0.f;
#pragma unroll 8
    for (int k = k0; k < k0 + chunk; k++) mx = fmaxf(mx, fabsf(W[(size_t)k * Nc + c]));
    partial[blockIdx.y * PSTRIDE + 2304 + j] = mx;
}

// transpose+quantize tile; reduces partial->scale inline, writes sB
__device__ __forceinline__ void wq_tile(const float* W, const float* partial,
    int pcolOff, float* sBout, char* o1, char* o0, int Nc, int Kd, int rowOff,
    int n0, int k0, int tid)
{
    __shared__ char s1[32][33], s0[32][33];
    int tx = tid & 31, tyg = tid >> 5;
    int n = n0 + tx;
    float mx = 0.f;
#pragma unroll
    for (int j = 0; j < 8; j++) mx = fmaxf(mx, partial[j * PSTRIDE + pcolOff + n]);
    mx = fmaxf(mx, 1e-20f);
    float inv = QMAX / mx;
    if (k0 == 0 && tyg == 0) sBout[rowOff + n] = mx / QMAX;
#pragma unroll
    for (int j = 0; j < 4; j++) {
        int kl = tyg * 4 + j;
        float v = W[(size_t)(k0 + kl) * Nc + n];
        quant_limbs(v, inv, s1[kl][tx], s0[kl][tx]);
    }
    __syncthreads();
#pragma unroll
    for (int j = 0; j < 4; j++) {
        int nl = tyg * 4 + j;
        size_t oidx = (size_t)(rowOff + n0 + nl) * Kd + k0 + tx;
        o1[oidx] = s1[tx][nl];
        o0[oidx] = s0[tx][nl];
    }
}

__global__ void __launch_bounds__(256) wquantT3_kernel(
    const float* __restrict__ Wq, const float* __restrict__ Wk, const float* __restrict__ Wv,
    const float* __restrict__ partial, float* __restrict__ sB,
    char* __restrict__ o1, char* __restrict__ o0)
{
    int z = blockIdx.z;
    const float* W = (z == 0) ? Wq : (z == 1) ? Wk : Wv;
    wq_tile(W, partial, z * 768, sB, o1, o0, 768, 768, z * 768,
            blockIdx.x * 32, blockIdx.y * 32, threadIdx.x);
}

__global__ void __launch_bounds__(256) wquantT_kernel(
    const float* __restrict__ W, const float* __restrict__ partial, int pcolOff,
    float* __restrict__ sB, char* __restrict__ o1, char* __restrict__ o0, int Nc, int Kd)
{
    wq_tile(W, partial, pcolOff, sB, o1, o0, Nc, Kd, 0,
            blockIdx.x * 32, blockIdx.y * 32, threadIdx.x);
}

// ---------------------------------------------------------------------------
// LayerNorm (+time emb) -> int8 limb planes + per-row scale
__global__ void __launch_bounds__(384) ln_quant_kernel(const float* __restrict__ x,
    const float* __restrict__ g, const float* __restrict__ be,
    const float* __restrict__ temb, char* __restrict__ o1, char* __restrict__ o0,
    float* __restrict__ sA)
{
    __shared__ float sb[13];
    int row = blockIdx.x, tid = threadIdx.x;
    int lane = tid & 31, w = tid >> 5;
    float2 xv = *(const float2*)(x + (size_t)row * DIMV + 2 * tid);
    float s = xv.x + xv.y;
#pragma unroll
    for (int o = 16; o; o >>= 1) s += __shfl_xor_sync(0xffffffffu, s, o);
    if (lane == 0) sb[w] = s;
    __syncthreads();
    if (w == 0) {
        float r = (lane < 12) ? sb[lane] : 0.f;
#pragma unroll
        for (int o = 16; o; o >>= 1) r += __shfl_xor_sync(0xffffffffu, r, o);
        if (lane == 0) sb[12] = r;
    }
    __syncthreads();
    float mu = sb[12] * (1.0f / DIMV);
    float dx = xv.x - mu, dy = xv.y - mu;
    float vs = dx * dx + dy * dy;
    __syncthreads();
#pragma unroll
    for (int o = 16; o; o >>= 1) vs += __shfl_xor_sync(0xffffffffu, vs, o);
    if (lane == 0) sb[w] = vs;
    __syncthreads();
    if (w == 0) {
        float r = (lane < 12) ? sb[lane] : 0.f;
#pragma unroll
        for (int o = 16; o; o >>= 1) r += __shfl_xor_sync(0xffffffffu, r, o);
        if (lane == 0) sb[12] = r;
    }
    __syncthreads();
    float inv = rsqrtf(sb[12] * (1.0f / DIMV) + 1e-5f);
    int b = row >> 11;
    int i0 = 2 * tid;
    float v0 = dx * inv * g[i0] + be[i0];
    float v1 = dy * inv * g[i0 + 1] + be[i0 + 1];
    if (temb) { v0 += temb[b * DIMV + i0]; v1 += temb[b * DIMV + i0 + 1]; }
    float mx = fmaxf(fabsf(v0), fabsf(v1));
    __syncthreads();
#pragma unroll
    for (int o = 16; o; o >>= 1) mx = fmaxf(mx, __shfl_xor_sync(0xffffffffu, mx, o));
    if (lane == 0) sb[w] = mx;
    __syncthreads();
    if (w == 0) {
        float r = (lane < 12) ? sb[lane] : 0.f;
#pragma unroll
        for (int o = 16; o; o >>= 1) r = fmaxf(r, __shfl_xor_sync(0xffffffffu, r, o));
        if (lane == 0) sb[12] = r;
    }
    __syncthreads();
    float rmax = fmaxf(sb[12], 1e-20f);
    float invs = QMAX / rmax;
    char a1, a0, b1, b0;
    quant_limbs(v0, invs, a1, a0);
    quant_limbs(v1, invs, b1, b0);
    size_t oi = (size_t)row * DIMV + i0;
    *(char2*)(o1 + oi) = make_char2(a1, b1);
    *(char2*)(o0 + oi) = make_char2(a0, b0);
    if (tid == 0) sA[row] = rmax / QMAX;
}

// ---------------------------------------------------------------------------
// int8 limb GEMM (3-pass). Block 128x128, 512 thr, BK=64, 4-stage cp.async.
// ---------------------------------------------------------------------------
#define O_A1 0
#define O_A0 8192
#define O_B1 16384
#define O_B0 24576
#define STG_BYTES 32768
#define GEMM_SMEM (4 * STG_BYTES)   // 128KB

__device__ __forceinline__ void cp16s(uint32_t sdst, const void* src) {
    asm volatile("cp.async.cg.shared.global [%0], [%1], 16;" :: "r"(sdst), "l"(src));
}
#define LDSM4(r, addr)                                                        \
    asm volatile("ldmatrix.sync.aligned.m8n8.x4.shared.b16 {%0,%1,%2,%3}, [%4];" \
        : "=r"((r)[0]), "=r"((r)[1]), "=r"((r)[2]), "=r"((r)[3]) : "r"(addr))
#define MMA_S8(d, a, b0, b1)                                                  \
    asm volatile(                                                             \
        "mma.sync.aligned.m16n8k32.row.col.s32.s8.s8.s32 "                    \
        "{%0,%1,%2,%3},{%4,%5,%6,%7},{%8,%9},{%0,%1,%2,%3};"                  \
        : "+r"((d)[0]), "+r"((d)[1]), "+r"((d)[2]), "+r"((d)[3])              \
        : "r"((a)[0]), "r"((a)[1]), "r"((a)[2]), "r"((a)[3]), "r"(b0), "r"(b1))

__global__ void __launch_bounds__(512, 1) s8_gemm_kernel(
    const char* __restrict__ A1, const char* __restrict__ A0,
    const char* __restrict__ B1, const char* __restrict__ B0,
    const float* __restrict__ sA, const float* __restrict__ sB,
    const float* __restrict__ bias, const float* __restrict__ res,
    float* __restrict__ Cf, int Nc, int K, int act)
{
    extern __shared__ __align__(128) char smc[];
    const int tid = threadIdx.x;
    const int warp = tid >> 5, lane = tid & 31;
    const int wm = warp & 3, wn = warp >> 2;
    const int g = lane >> 2, t = lane & 3;
    const int bm = blockIdx.y * 128, bn = blockIdx.x * 128;
    const int nk = K >> 6;

    uint32_t sbase;
    asm("{ .reg .u64 tt; cvta.to.shared.u64 tt, %1; cvt.u32.u64 %0, tt; }"
        : "=r"(sbase) : "l"(smc));

    const int arl = lane & 15, aqb = lane >> 4;
    const int arsw = (arl >> 1) & 3;
    uint32_t aoff[2], aq[2];
#pragma unroll
    for (int mi = 0; mi < 2; mi++)
        aoff[mi] = (uint32_t)(wm * 32 + mi * 16 + arl) * 64u;
#pragma unroll
    for (int ks = 0; ks < 2; ks++)
        aq[ks] = (uint32_t)(((2 * ks + aqb) ^ arsw) << 4);
    const int nrl = (lane & 7) + ((lane >> 4) << 3);
    const int bqb = (lane >> 3) & 1;
    const int brsw = (nrl >> 1) & 3;
    uint32_t boff[2], bq[2];
#pragma unroll
    for (int ni = 0; ni < 2; ni++)
        boff[ni] = (uint32_t)(wn * 32 + ni * 16 + nrl) * 64u;
#pragma unroll
    for (int ks = 0; ks < 2; ks++)
        bq[ks] = (uint32_t)(((2 * ks + bqb) ^ brsw) << 4);

    int hh[2][2][2][4], cx[2][2][2][4];
#pragma unroll
    for (int mi = 0; mi < 2; mi++)
#pragma unroll
        for (int ni = 0; ni < 2; ni++)
#pragma unroll
            for (int pr = 0; pr < 2; pr++)
#pragma unroll
                for (int e = 0; e < 4; e++) { hh[mi][ni][pr][e] = 0; cx[mi][ni][pr][e] = 0; }

    auto load_stage = [&](int buf, int it) {
        if (it < nk) {
            uint32_t st = sbase + buf * STG_BYTES;
            int kb = it * 64;
            int m = tid >> 2, q = tid & 3;
            uint32_t woff = (uint32_t)(m * 64 + ((q ^ ((m >> 1) & 3)) << 4));
            size_t ga = (size_t)(bm + m) * K + kb + q * 16;
            cp16s(st + O_A1 + woff, A1 + ga);
            cp16s(st + O_A0 + woff, A0 + ga);
            size_t gb = (size_t)(bn + m) * K + kb + q * 16;
            cp16s(st + O_B1 + woff, B1 + gb);
            cp16s(st + O_B0 + woff, B0 + gb);
        }
        asm volatile("cp.async.commit_group;");
    };

    load_stage(0, 0);
    load_stage(1, 1);
    load_stage(2, 2);

    for (int it = 0; it < nk; it++) {
        asm volatile("cp.async.wait_group 2;");
        __syncthreads();
        load_stage((it + 3) & 3, it + 3);

        uint32_t st = sbase + (it & 3) * STG_BYTES;
#pragma unroll
        for (int ks = 0; ks < 2; ks++) {
            uint32_t fA1[2][4], fA0[2][4], fB1[2][4], fB0[2][4];
#pragma unroll
            for (int mi = 0; mi < 2; mi++)
                LDSM4(fA1[mi], st + O_A1 + aoff[mi] + aq[ks]);
#pragma unroll
            for (int ni = 0; ni < 2; ni++)
                LDSM4(fB1[ni], st + O_B1 + boff[ni] + bq[ks]);
#pragma unroll
            for (int mi = 0; mi < 2; mi++)
#pragma unroll
                for (int ni = 0; ni < 2; ni++)
#pragma unroll
                    for (int pr = 0; pr < 2; pr++)
                        MMA_S8(hh[mi][ni][pr], fA1[mi], fB1[ni][2 * pr], fB1[ni][2 * pr + 1]);
#pragma unroll
            for (int ni = 0; ni < 2; ni++)
                LDSM4(fB0[ni], st + O_B0 + boff[ni] + bq[ks]);
#pragma unroll
            for (int mi = 0; mi < 2; mi++)
#pragma unroll
                for (int ni = 0; ni < 2; ni++)
#pragma unroll
                    for (int pr = 0; pr < 2; pr++)
                        MMA_S8(cx[mi][ni][pr], fA1[mi], fB0[ni][2 * pr], fB0[ni][2 * pr + 1]);
#pragma unroll
            for (int mi = 0; mi < 2; mi++)
                LDSM4(fA0[mi], st + O_A0 + aoff[mi] + aq[ks]);
#pragma unroll
            for (int mi = 0; mi < 2; mi++)
#pragma unroll
                for (int ni = 0; ni < 2; ni++)
#pragma unroll
                    for (int pr = 0; pr < 2; pr++)
                        MMA_S8(cx[mi][ni][pr], fA0[mi], fB1[ni][2 * pr], fB1[ni][2 * pr + 1]);
        }
    }

#pragma unroll
    for (int mi = 0; mi < 2; mi++) {
#pragma unroll
        for (int ni = 0; ni < 2; ni++) {
#pragma unroll
            for (int pr = 0; pr < 2; pr++) {
                int col = bn + wn * 32 + ni * 16 + pr * 8 + 2 * t;
                float2 sb2 = *(const float2*)(sB + col);
                float2 bb = *(const float2*)(bias + col);
#pragma unroll
                for (int hf = 0; hf < 2; hf++) {
                    int r = bm + wm * 32 + mi * 16 + g + hf * 8;
                    float sa = sA[r];
                    float vx = sa * sb2.x * (16384.f * (float)hh[mi][ni][pr][2 * hf]
                              + 128.f * (float)cx[mi][ni][pr][2 * hf]) + bb.x;
                    float vy = sa * sb2.y * (16384.f * (float)hh[mi][ni][pr][2 * hf + 1]
                              + 128.f * (float)cx[mi][ni][pr][2 * hf + 1]) + bb.y;
                    if (act) { vx = gelu_f(vx); vy = gelu_f(vy); }
                    if (res) {
                        const float2 rr = *(const float2*)(res + (size_t)r * Nc + col);
                        vx += rr.x; vy += rr.y;
                    }
                    float2 o; o.x = vx; o.y = vy;
                    *(float2*)(Cf + (size_t)r * Nc + col) = o;
                }
            }
        }
    }
}

// ---------------------------------------------------------------------------
// ffn row quant
__global__ void __launch_bounds__(256) ffn_quant_kernel(const float* __restrict__ f,
    char* __restrict__ o1, char* __restrict__ o0, float* __restrict__ sA)
{
    __shared__ float sb[9];
    int row = blockIdx.x, tid = threadIdx.x;
    int lane = tid & 31, w = tid >> 5;
    const float4* base = (const float4*)(f + (size_t)row * DFF);
    float mx = 0.f;
#pragma unroll
    for (int i = 0; i < 3; i++) {
        float4 v = base[tid + i * 256];
        mx = fmaxf(mx, fmaxf(fmaxf(fabsf(v.x), fabsf(v.y)), fmaxf(fabsf(v.z), fabsf(v.w))));
    }
#pragma unroll
    for (int o = 16; o; o >>= 1) mx = fmaxf(mx, __shfl_xor_sync(0xffffffffu, mx, o));
    if (lane == 0) sb[w] = mx;
    __syncthreads();
    if (w == 0) {
        float r = (lane < 8) ? sb[lane] : 0.f;
#pragma unroll
        for (int o = 4; o; o >>= 1) r = fmaxf(r, __shfl_xor_sync(0xffffffffu, r, o));
        if (lane == 0) sb[8] = r;
    }
    __syncthreads();
    float rmax = fmaxf(sb[8], 1e-20f);
    float inv = QMAX / rmax;
    uint32_t* p1 = (uint32_t*)(o1 + (size_t)row * DFF);
    uint32_t* p0 = (uint32_t*)(o0 + (size_t)row * DFF);
#pragma unroll
    for (int i = 0; i < 3; i++) {
        float4 v = base[tid + i * 256];
        char a1, a0, b1, b0, c1, c0, d1, d0;
        quant_limbs(v.x, inv, a1, a0);
        quant_limbs(v.y, inv, b1, b0);
        quant_limbs(v.z, inv, c1, c0);
        quant_limbs(v.w, inv, d1, d0);
        p1[tid + i * 256] = (uint32_t)(uint8_t)a1 | ((uint32_t)(uint8_t)b1 << 8)
                          | ((uint32_t)(uint8_t)c1 << 16) | ((uint32_t)(uint8_t)d1 << 24);
        p0[tid + i * 256] = (uint32_t)(uint8_t)a0 | ((uint32_t)(uint8_t)b0 << 8)
                          | ((uint32_t)(uint8_t)c0 << 16) | ((uint32_t)(uint8_t)d0 << 24);
    }
    if (tid == 0) sA[row] = rmax / QMAX;
}

// ---------------------------------------------------------------------------
// Poincare top-KNN: 2 rows/block, 256 threads, 32KB static smem.
// Phase 1 twice (once per row); phase 2 on warps 0-1 (one row each).
// key64 = (float_bits << 32) | idx  — unsigned order == (val, idx) lexicographic.
// ---------------------------------------------------------------------------
__device__ __forceinline__ void ce64(unsigned long long& a, unsigned long long& b) {
    unsigned long long lo = min(a, b), hi = max(a, b);
    a = lo; b = hi;
}

__global__ void __launch_bounds__(256) topk2_kernel(const float* __restrict__ pos,
    const float* __restrict__ cptr, int* __restrict__ idxo, float* __restrict__ disto)
{
    __shared__ unsigned long long skv[2 * NTOK];      // 32 KB
    int tid = threadIdx.x;
    int base = blockIdx.x * 2;
    int b = base >> 11;
    float c = cptr[0];
    float inv_sqc = rsqrtf(c);
    const float* pb = pos + (size_t)b * NTOK * 2;

#pragma unroll
    for (int r2 = 0; r2 < 2; r2++) {
        int i = (base + r2) & (NTOK - 1);
        float yx = pb[i * 2], yy = pb[i * 2 + 1];
        float denY = 1.f - c * (yx * yx + yy * yy);
        unsigned long long k[8];
#pragma unroll
        for (int u = 0; u < 8; u++) {
            int j = tid + u * 256;
            float2 pj = *(const float2*)(pb + j * 2);
            float dx = pj.x - yx, dy = pj.y - yy;
            float num = 2.f * c * (dx * dx + dy * dy);
            float den = (1.f - c * (pj.x * pj.x + pj.y * pj.y)) * denY;
            float v = fmaxf(1.f + num / (den + 1e-8f), 1.f);
            k[u] = ((unsigned long long)__float_as_uint(v) << 32) | (unsigned)j;
        }
        ce64(k[0],k[1]); ce64(k[2],k[3]); ce64(k[4],k[5]); ce64(k[6],k[7]);
        ce64(k[0],k[2]); ce64(k[1],k[3]); ce64(k[4],k[6]); ce64(k[5],k[7]);
        ce64(k[1],k[2]); ce64(k[5],k[6]);
        ce64(k[0],k[4]); ce64(k[1],k[5]); ce64(k[2],k[6]); ce64(k[3],k[7]);
        ce64(k[2],k[4]); ce64(k[3],k[5]);
        ce64(k[1],k[2]); ce64(k[3],k[4]); ce64(k[5],k[6]);
#pragma unroll
        for (int u = 0; u < 8; u++) skv[r2 * NTOK + tid * 8 + u] = k[u];
    }
    __syncthreads();
    if (tid >= 64) return;                 // warps 2-7 retire

    int w = tid >> 5, lane = tid & 31;
    unsigned long long* rs = skv + w * NTOK;
    unsigned long long head[8];
    int ptr[8];
#pragma unroll
    for (int h = 0; h < 8; h++) { head[h] = rs[(lane * 8 + h) * 8]; ptr[h] = 0; }
    unsigned long long lmin = head[0]; int lh = 0;
#pragma unroll
    for (int h = 1; h < 8; h++)
        if (head[h] < lmin) { lmin = head[h]; lh = h; }

    unsigned long long mykey = 0xFFFFFFFFFFFFFFFFull;
    for (int sel = 0; sel < KNN; sel++) {
        unsigned long long bk = lmin; int bl = lane;
#pragma unroll
        for (int o = 16; o; o >>= 1) {
            unsigned long long ok = __shfl_xor_sync(0xffffffffu, bk, o);
            int ol = __shfl_xor_sync(0xffffffffu, bl, o);
            if (ok < bk) { bk = ok; bl = ol; }
        }
        if (lane == sel) mykey = bk;
        if (lane == bl) {
            int pp = ++ptr[lh];
            head[lh] = (pp < 8) ? rs[(lane * 8 + lh) * 8 + pp] : 0xFFFFFFFFFFFFFFFFull;
            lmin = head[0]; lh = 0;
#pragma unroll
            for (int h = 1; h < 8; h++)
                if (head[h] < lmin) { lmin = head[h]; lh = h; }
        }
    }
    int row = base + w;
    float v = __uint_as_float((unsigned)(mykey >> 32));
    idxo[(size_t)row * KNN + lane] = (int)(unsigned)(mykey & 0xFFFFFFFFull);
    disto[(size_t)row * KNN + lane] = acoshf(v) * inv_sqc;
}

// ---------------------------------------------------------------------------
// kNN attention: batched fp32 gather loads (MLP 16), int8-limb output + scale
__global__ void __launch_bounds__(384) attn_quant_kernel(const float* __restrict__ qkv,
    const int* __restrict__ idx, const float* __restrict__ dist,
    const float* __restrict__ log_tau,
    char* __restrict__ o1, char* __restrict__ o0, float* __restrict__ sA)
{
    __shared__ int sidx[KNN];
    __shared__ float sgeo[KNN];
    __shared__ float smax[13];
    int row = blockIdx.x;
    int lane = threadIdx.x & 31, h = threadIdx.x >> 5;
    float invtau = 1.f / (expf(log_tau[0]) + 1e-8f);
    if (threadIdx.x < KNN) {
        sidx[threadIdx.x] = idx[(size_t)row * KNN + threadIdx.x];
        sgeo[threadIdx.x] = -dist[(size_t)row * KNN + threadIdx.x] * invtau;
    }
    __syncthreads();
    int b = row >> 11;
    const float* qp = qkv + (size_t)row * 2304 + h * HDIM;
    float q0 = qp[2 * lane], q1 = qp[2 * lane + 1];
    const float* kb = qkv + (size_t)b * NTOK * 2304 + 768 + h * HDIM;
    const float* vb = qkv + (size_t)b * NTOK * 2304 + 1536 + h * HDIM;
    float myscore = 0.f;
#pragma unroll
    for (int j0 = 0; j0 < KNN; j0 += 8) {
        float ka[8], kc[8];
#pragma unroll
        for (int u = 0; u < 8; u++) {
            const float2 kv2 = *(const float2*)(kb + (size_t)sidx[j0 + u] * 2304 + 2 * lane);
            ka[u] = kv2.x; kc[u] = kv2.y;
        }
#pragma unroll
        for (int u = 0; u < 8; u++) {
            float p = q0 * ka[u] + q1 * kc[u];
#pragma unroll
            for (int o = 16; o; o >>= 1) p += __shfl_xor_sync(0xffffffffu, p, o);
            if (lane == j0 + u) myscore = p * 0.125f + sgeo[j0 + u];
        }
    }
    float m = myscore;
#pragma unroll
    for (int o = 16; o; o >>= 1) m = fmaxf(m, __shfl_xor_sync(0xffffffffu, m, o));
    float e = expf(myscore - m);
    float s = e;
#pragma unroll
    for (int o = 16; o; o >>= 1) s += __shfl_xor_sync(0xffffffffu, s, o);
    float p = e / s;
    float v0 = 0.f, v1 = 0.f;
#pragma unroll
    for (int j0 = 0; j0 < KNN; j0 += 8) {
        float va[8], vc[8];
#pragma unroll
        for (int u = 0; u < 8; u++) {
            const float2 vv2 = *(const float2*)(vb + (size_t)sidx[j0 + u] * 2304 + 2 * lane);
            va[u] = vv2.x; vc[u] = vv2.y;
        }
#pragma unroll
        for (int u = 0; u < 8; u++) {
            float pj = __shfl_sync(0xffffffffu, p, j0 + u);
            v0 += pj * va[u]; v1 += pj * vc[u];
        }
    }
    float mx = fmaxf(fabsf(v0), fabsf(v1));
#pragma unroll
    for (int o = 16; o; o >>= 1) mx = fmaxf(mx, __shfl_xor_sync(0xffffffffu, mx, o));
    if (lane == 0) smax[h] = mx;
    __syncthreads();
    if (h == 0) {
        float r = (lane < 12) ? smax[lane] : 0.f;
#pragma unroll
        for (int o = 16; o; o >>= 1) r = fmaxf(r, __shfl_xor_sync(0xffffffffu, r, o));
        if (lane == 0) smax[12] = r;
    }
    __syncthreads();
    float rmax = fmaxf(smax[12], 1e-20f);
    float inv = QMAX / rmax;
    char a1, a0, b1c, b0c;
    quant_limbs(v0, inv, a1, a0);
    quant_limbs(v1, inv, b1c, b0c);
    size_t oi = (size_t)row * DIMV + h * HDIM + 2 * lane;
    *(char2*)(o1 + oi) = make_char2(a1, b1c);
    *(char2*)(o0 + oi) = make_char2(a0, b0c);
    if (threadIdx.x == 0) sA[row] = rmax / QMAX;
}

// ---------------------------------------------------------------------------
extern "C" void kernel_launch(void* const* d_in, const int* in_sizes, int n_in,
                              void* d_out, int out_size)
{
    const float* x    = (const float*)d_in[0];
    const float* pos  = (const float*)d_in[1];
    const float* c    = (const float*)d_in[2];
    const float* temb = (const float*)d_in[3];
    const float* Wq = (const float*)d_in[4],  *bq = (const float*)d_in[5];
    const float* Wk = (const float*)d_in[6],  *bk = (const float*)d_in[7];
    const float* Wv = (const float*)d_in[8],  *bv = (const float*)d_in[9];
    const float* Wo = (const float*)d_in[10], *bo = (const float*)d_in[11];
    const float* W1 = (const float*)d_in[12], *b1 = (const float*)d_in[13];
    const float* W2 = (const float*)d_in[14], *b2 = (const float*)d_in[15];
    const float* g1 = (const float*)d_in[16], *be1 = (const float*)d_in[17];
    const float* g2 = (const float*)d_in[18], *be2 = (const float*)d_in[19];
    const float* log_tau = (const float*)d_in[20];
    float* out = (float*)d_out;

    char* arena; cudaGetSymbolAddress((void**)&arena, g_arena);
    int* idxp;   cudaGetSymbolAddress((void**)&idxp, g_idx);
    float* distp;cudaGetSymbolAddress((void**)&distp, g_dist);

    char* p = arena;
    auto carve = [&](size_t bytes) { char* r = p; p += (bytes + 127) & ~(size_t)127; return r; };
    char* h1   = carve((size_t)MROWS * 768);
    char* h0   = carve((size_t)MROWS * 768);
    char* att1 = carve((size_t)MROWS * 768);
    char* att0 = carve((size_t)MROWS * 768);
    char* h21  = carve((size_t)MROWS * 768);
    char* h20  = carve((size_t)MROWS * 768);
    char* ffn1 = carve((size_t)MROWS * 3072);
    char* ffn0 = carve((size_t)MROWS * 3072);
    char* wqkv1 = carve((size_t)2304 * 768);
    char* wqkv0 = carve((size_t)2304 * 768);
    char* wo1  = carve((size_t)768 * 768);
    char* wo0  = carve((size_t)768 * 768);
    char* w11  = carve((size_t)3072 * 768);
    char* w10  = carve((size_t)3072 * 768);
    char* w21  = carve((size_t)768 * 3072);
    char* w20  = carve((size_t)768 * 3072);
    float* qkv   = (float*)carve((size_t)MROWS * 2304 * 4);
    float* x2    = (float*)carve((size_t)MROWS * 768 * 4);
    float* ffn_f = (float*)carve((size_t)MROWS * 3072 * 4);
    float* partial = (float*)carve(8 * PSTRIDE * 4);
    float* sAh   = (float*)carve(MROWS * 4);
    float* sAatt = (float*)carve(MROWS * 4);
    float* sAh2  = (float*)carve(MROWS * 4);
    float* sAffn = (float*)carve(MROWS * 4);
    float* sBqkv = (float*)carve(2304 * 4);
    float* sBo   = (float*)carve(768 * 4);
    float* sB1   = (float*)carve(3072 * 4);
    float* sB2   = (float*)carve(768 * 4);
    float* bqkv  = (float*)carve(2304 * 4);

    cudaFuncSetAttribute(s8_gemm_kernel,
                         cudaFuncAttributeMaxDynamicSharedMemorySize, GEMM_SMEM);

    // launches 1-3, then topk2 as launch 4 (= ncu capture slot)
    ln_quant_kernel<<<MROWS, 384>>>(x, g1, be1, temb, h1, h0, sAh);
    wpmax_qkv_kernel<<<dim3(9, 8), 256>>>(Wq, Wk, Wv, bq, bk, bv, partial, bqkv);
    wquantT3_kernel<<<dim3(24, 24, 3), 256>>>(Wq, Wk, Wv, partial, sBqkv, wqkv1, wqkv0);
    topk2_kernel<<<MROWS / 2, 256>>>(pos, c, idxp, distp);

    s8_gemm_kernel<<<dim3(18, 32), 512, GEMM_SMEM>>>(h1, h0, wqkv1, wqkv0,
        sAh, sBqkv, bqkv, nullptr, qkv, 2304, 768, 0);
    attn_quant_kernel<<<MROWS, 384>>>(qkv, idxp, distp, log_tau, att1, att0, sAatt);

    wpmax_rest_kernel<<<dim3(18, 8), 256>>>(Wo, W1, W2, partial);
    wquantT_kernel<<<dim3(24, 24), 256>>>(Wo, partial, 2304, sBo, wo1, wo0, 768, 768);
    wquantT_kernel<<<dim3(96, 24), 256>>>(W1, partial, 3072, sB1, w11, w10, 3072, 768);
    wquantT_kernel<<<dim3(24, 96), 256>>>(W2, partial, 6144, sB2, w21, w20, 768, 3072);

    // x2 = x + att @ Wo
    s8_gemm_kernel<<<dim3(6, 32), 512, GEMM_SMEM>>>(att1, att0, wo1, wo0,
        sAatt, sBo, bo, x, x2, 768, 768, 0);
    ln_quant_kernel<<<MROWS, 384>>>(x2, g2, be2, nullptr, h21, h20, sAh2);

    // ffn_f = gelu(h2 @ W1)
    s8_gemm_kernel<<<dim3(24, 32), 512, GEMM_SMEM>>>(h21, h20, w11, w10,
        sAh2, sB1, b1, nullptr, ffn_f, 3072, 768, 1);
    ffn_quant_kernel<<<MROWS, 256>>>(ffn_f, ffn1, ffn0, sAffn);

    // out = x2 + ffn @ W2
    s8_gemm_kernel<<<dim3(6, 32), 512, GEMM_SMEM>>>(ffn1, ffn0, w21, w20,
        sAffn, sB2, b2, x2, out, 768, 3072, 0);
}

// round 16
// speedup vs baseline: 1.1214x; 1.0390x over previous
#include <cuda_runtime.h>
#include <cuda_bf16.h>
#include <math.h>
#include <stdint.h>

#define NTOK 2048
#define BATCH 2
#define DIMV 768
#define NHEAD 12
#define HDIM 64
#define KNN 32
#define DFF 3072
#define MROWS 4096
#define QMAX 16256.0f
#define PSTRIDE 8192

#define ARENA_BYTES 172000000ull
__device__ __align__(128) char g_arena[ARENA_BYTES];
__device__ int   g_idx[MROWS * KNN];
__device__ float g_dist[MROWS * KNN];

// ---------------------------------------------------------------------------
__device__ __forceinline__ float gelu_f(float v) {
    return 0.5f * v * (1.f + erff(v * 0.70710678118654752f));
}
__device__ __forceinline__ void quant_limbs(float v, float inv_s, char& q1c, char& q0c) {
    int q = __float2int_rn(v * inv_s);
    q = max(-16256, min(16256, q));
    int q1 = (q + 64) >> 7;
    int q0 = q - (q1 << 7);
    q1c = (char)q1; q0c = (char)q0;
}

// ---------------------------------------------------------------------------
// parallel per-column absmax, 8 K-chunks; qkv variant also concats bias
__global__ void __launch_bounds__(256) wpmax_qkv_kernel(
    const float* __restrict__ Wq, const float* __restrict__ Wk, const float* __restrict__ Wv,
    const float* __restrict__ bq, const float* __restrict__ bk, const float* __restrict__ bv,
    float* __restrict__ partial, float* __restrict__ bqkv)
{
    int col = blockIdx.x * 256 + threadIdx.x;        // 0..2303
    int w = col / 768, c = col - w * 768;
    const float* W = (w == 0) ? Wq : (w == 1) ? Wk : Wv;
    int k0 = blockIdx.y * 96;
    float mx = 0.f;
#pragma unroll 8
    for (int k = k0; k < k0 + 96; k++) mx = fmaxf(mx, fabsf(W[(size_t)k * 768 + c]));
    partial[blockIdx.y * PSTRIDE + col] = mx;
    if (blockIdx.y == 0)
        bqkv[col] = ((w == 0) ? bq : (w == 1) ? bk : bv)[c];
}

__global__ void __launch_bounds__(256) wpmax_rest_kernel(
    const float* __restrict__ Wo, const float* __restrict__ W1, const float* __restrict__ W2,
    float* __restrict__ partial)
{
    int j = blockIdx.x * 256 + threadIdx.x;          // 0..4607
    const float* W; int c, K, Nc;
    if (j < 768)       { W = Wo; c = j;        K = 768;  Nc = 768;  }
    else if (j < 3840) { W = W1; c = j - 768;  K = 768;  Nc = 3072; }
    else               { W = W2; c = j - 3840; K = 3072; Nc = 768;  }
    int chunk = K >> 3;
    int k0 = blockIdx.y * chunk;
    float mx = 0.f;
#pragma unroll 8
    for (int k = k0; k < k0 + chunk; k++) mx = fmaxf(mx, fabsf(W[(size_t)k * Nc + c]));
    partial[blockIdx.y * PSTRIDE + 2304 + j] = mx;
}

// transpose+quantize tile; reduces partial->scale inline, writes sB
__device__ __forceinline__ void wq_tile(const float* W, const float* partial,
    int pcolOff, float* sBout, char* o1, char* o0, int Nc, int Kd, int rowOff,
    int n0, int k0, int tid)
{
    __shared__ char s1[32][33], s0[32][33];
    int tx = tid & 31, tyg = tid >> 5;
    int n = n0 + tx;
    float mx = 0.f;
#pragma unroll
    for (int j = 0; j < 8; j++) mx = fmaxf(mx, partial[j * PSTRIDE + pcolOff + n]);
    mx = fmaxf(mx, 1e-20f);
    float inv = QMAX / mx;
    if (k0 == 0 && tyg == 0) sBout[rowOff + n] = mx / QMAX;
#pragma unroll
    for (int j = 0; j < 4; j++) {
        int kl = tyg * 4 + j;
        float v = W[(size_t)(k0 + kl) * Nc + n];
        quant_limbs(v, inv, s1[kl][tx], s0[kl][tx]);
    }
    __syncthreads();
#pragma unroll
    for (int j = 0; j < 4; j++) {
        int nl = tyg * 4 + j;
        size_t oidx = (size_t)(rowOff + n0 + nl) * Kd + k0 + tx;
        o1[oidx] = s1[tx][nl];
        o0[oidx] = s0[tx][nl];
    }
}

__global__ void __launch_bounds__(256) wquantT3_kernel(
    const float* __restrict__ Wq, const float* __restrict__ Wk, const float* __restrict__ Wv,
    const float* __restrict__ partial, float* __restrict__ sB,
    char* __restrict__ o1, char* __restrict__ o0)
{
    int z = blockIdx.z;
    const float* W = (z == 0) ? Wq : (z == 1) ? Wk : Wv;
    wq_tile(W, partial, z * 768, sB, o1, o0, 768, 768, z * 768,
            blockIdx.x * 32, blockIdx.y * 32, threadIdx.x);
}

__global__ void __launch_bounds__(256) wquantT_kernel(
    const float* __restrict__ W, const float* __restrict__ partial, int pcolOff,
    float* __restrict__ sB, char* __restrict__ o1, char* __restrict__ o0, int Nc, int Kd)
{
    wq_tile(W, partial, pcolOff, sB, o1, o0, Nc, Kd, 0,
            blockIdx.x * 32, blockIdx.y * 32, threadIdx.x);
}

// ---------------------------------------------------------------------------
// LayerNorm (+time emb) -> int8 limb planes + per-row scale
__global__ void __launch_bounds__(384) ln_quant_kernel(const float* __restrict__ x,
    const float* __restrict__ g, const float* __restrict__ be,
    const float* __restrict__ temb, char* __restrict__ o1, char* __restrict__ o0,
    float* __restrict__ sA)
{
    __shared__ float sb[13];
    int row = blockIdx.x, tid = threadIdx.x;
    int lane = tid & 31, w = tid >> 5;
    float2 xv = *(const float2*)(x + (size_t)row * DIMV + 2 * tid);
    float s = xv.x + xv.y;
#pragma unroll
    for (int o = 16; o; o >>= 1) s += __shfl_xor_sync(0xffffffffu, s, o);
    if (lane == 0) sb[w] = s;
    __syncthreads();
    if (w == 0) {
        float r = (lane < 12) ? sb[lane] : 0.f;
#pragma unroll
        for (int o = 16; o; o >>= 1) r += __shfl_xor_sync(0xffffffffu, r, o);
        if (lane == 0) sb[12] = r;
    }
    __syncthreads();
    float mu = sb[12] * (1.0f / DIMV);
    float dx = xv.x - mu, dy = xv.y - mu;
    float vs = dx * dx + dy * dy;
    __syncthreads();
#pragma unroll
    for (int o = 16; o; o >>= 1) vs += __shfl_xor_sync(0xffffffffu, vs, o);
    if (lane == 0) sb[w] = vs;
    __syncthreads();
    if (w == 0) {
        float r = (lane < 12) ? sb[lane] : 0.f;
#pragma unroll
        for (int o = 16; o; o >>= 1) r += __shfl_xor_sync(0xffffffffu, r, o);
        if (lane == 0) sb[12] = r;
    }
    __syncthreads();
    float inv = rsqrtf(sb[12] * (1.0f / DIMV) + 1e-5f);
    int b = row >> 11;
    int i0 = 2 * tid;
    float v0 = dx * inv * g[i0] + be[i0];
    float v1 = dy * inv * g[i0 + 1] + be[i0 + 1];
    if (temb) { v0 += temb[b * DIMV + i0]; v1 += temb[b * DIMV + i0 + 1]; }
    float mx = fmaxf(fabsf(v0), fabsf(v1));
    __syncthreads();
#pragma unroll
    for (int o = 16; o; o >>= 1) mx = fmaxf(mx, __shfl_xor_sync(0xffffffffu, mx, o));
    if (lane == 0) sb[w] = mx;
    __syncthreads();
    if (w == 0) {
        float r = (lane < 12) ? sb[lane] : 0.f;
#pragma unroll
        for (int o = 16; o; o >>= 1) r = fmaxf(r, __shfl_xor_sync(0xffffffffu, r, o));
        if (lane == 0) sb[12] = r;
    }
    __syncthreads();
    float rmax = fmaxf(sb[12], 1e-20f);
    float invs = QMAX / rmax;
    char a1, a0, b1, b0;
    quant_limbs(v0, invs, a1, a0);
    quant_limbs(v1, invs, b1, b0);
    size_t oi = (size_t)row * DIMV + i0;
    *(char2*)(o1 + oi) = make_char2(a1, b1);
    *(char2*)(o0 + oi) = make_char2(a0, b0);
    if (tid == 0) sA[row] = rmax / QMAX;
}

// ---------------------------------------------------------------------------
// int8 limb GEMM (3-pass). Block 128x128, 512 thr, BK=64, 4-stage cp.async.
// ---------------------------------------------------------------------------
#define O_A1 0
#define O_A0 8192
#define O_B1 16384
#define O_B0 24576
#define STG_BYTES 32768
#define GEMM_SMEM (4 * STG_BYTES)   // 128KB

__device__ __forceinline__ void cp16s(uint32_t sdst, const void* src) {
    asm volatile("cp.async.cg.shared.global [%0], [%1], 16;" :: "r"(sdst), "l"(src));
}
#define LDSM4(r, addr)                                                        \
    asm volatile("ldmatrix.sync.aligned.m8n8.x4.shared.b16 {%0,%1,%2,%3}, [%4];" \
        : "=r"((r)[0]), "=r"((r)[1]), "=r"((r)[2]), "=r"((r)[3]) : "r"(addr))
#define MMA_S8(d, a, b0, b1)                                                  \
    asm volatile(                                                             \
        "mma.sync.aligned.m16n8k32.row.col.s32.s8.s8.s32 "                    \
        "{%0,%1,%2,%3},{%4,%5,%6,%7},{%8,%9},{%0,%1,%2,%3};"                  \
        : "+r"((d)[0]), "+r"((d)[1]), "+r"((d)[2]), "+r"((d)[3])              \
        : "r"((a)[0]), "r"((a)[1]), "r"((a)[2]), "r"((a)[3]), "r"(b0), "r"(b1))

__global__ void __launch_bounds__(512, 1) s8_gemm_kernel(
    const char* __restrict__ A1, const char* __restrict__ A0,
    const char* __restrict__ B1, const char* __restrict__ B0,
    const float* __restrict__ sA, const float* __restrict__ sB,
    const float* __restrict__ bias, const float* __restrict__ res,
    float* __restrict__ Cf, int Nc, int K, int act)
{
    extern __shared__ __align__(128) char smc[];
    const int tid = threadIdx.x;
    const int warp = tid >> 5, lane = tid & 31;
    const int wm = warp & 3, wn = warp >> 2;
    const int g = lane >> 2, t = lane & 3;
    const int bm = blockIdx.y * 128, bn = blockIdx.x * 128;
    const int nk = K >> 6;

    uint32_t sbase;
    asm("{ .reg .u64 tt; cvta.to.shared.u64 tt, %1; cvt.u32.u64 %0, tt; }"
        : "=r"(sbase) : "l"(smc));

    const int arl = lane & 15, aqb = lane >> 4;
    const int arsw = (arl >> 1) & 3;
    uint32_t aoff[2], aq[2];
#pragma unroll
    for (int mi = 0; mi < 2; mi++)
        aoff[mi] = (uint32_t)(wm * 32 + mi * 16 + arl) * 64u;
#pragma unroll
    for (int ks = 0; ks < 2; ks++)
        aq[ks] = (uint32_t)(((2 * ks + aqb) ^ arsw) << 4);
    const int nrl = (lane & 7) + ((lane >> 4) << 3);
    const int bqb = (lane >> 3) & 1;
    const int brsw = (nrl >> 1) & 3;
    uint32_t boff[2], bq[2];
#pragma unroll
    for (int ni = 0; ni < 2; ni++)
        boff[ni] = (uint32_t)(wn * 32 + ni * 16 + nrl) * 64u;
#pragma unroll
    for (int ks = 0; ks < 2; ks++)
        bq[ks] = (uint32_t)(((2 * ks + bqb) ^ brsw) << 4);

    int hh[2][2][2][4], cx[2][2][2][4];
#pragma unroll
    for (int mi = 0; mi < 2; mi++)
#pragma unroll
        for (int ni = 0; ni < 2; ni++)
#pragma unroll
            for (int pr = 0; pr < 2; pr++)
#pragma unroll
                for (int e = 0; e < 4; e++) { hh[mi][ni][pr][e] = 0; cx[mi][ni][pr][e] = 0; }

    auto load_stage = [&](int buf, int it) {
        if (it < nk) {
            uint32_t st = sbase + buf * STG_BYTES;
            int kb = it * 64;
            int m = tid >> 2, q = tid & 3;
            uint32_t woff = (uint32_t)(m * 64 + ((q ^ ((m >> 1) & 3)) << 4));
            size_t ga = (size_t)(bm + m) * K + kb + q * 16;
            cp16s(st + O_A1 + woff, A1 + ga);
            cp16s(st + O_A0 + woff, A0 + ga);
            size_t gb = (size_t)(bn + m) * K + kb + q * 16;
            cp16s(st + O_B1 + woff, B1 + gb);
            cp16s(st + O_B0 + woff, B0 + gb);
        }
        asm volatile("cp.async.commit_group;");
    };

    load_stage(0, 0);
    load_stage(1, 1);
    load_stage(2, 2);

    for (int it = 0; it < nk; it++) {
        asm volatile("cp.async.wait_group 2;");
        __syncthreads();
        load_stage((it + 3) & 3, it + 3);

        uint32_t st = sbase + (it & 3) * STG_BYTES;
#pragma unroll
        for (int ks = 0; ks < 2; ks++) {
            uint32_t fA1[2][4], fA0[2][4], fB1[2][4], fB0[2][4];
#pragma unroll
            for (int mi = 0; mi < 2; mi++)
                LDSM4(fA1[mi], st + O_A1 + aoff[mi] + aq[ks]);
#pragma unroll
            for (int ni = 0; ni < 2; ni++)
                LDSM4(fB1[ni], st + O_B1 + boff[ni] + bq[ks]);
#pragma unroll
            for (int mi = 0; mi < 2; mi++)
#pragma unroll
                for (int ni = 0; ni < 2; ni++)
#pragma unroll
                    for (int pr = 0; pr < 2; pr++)
                        MMA_S8(hh[mi][ni][pr], fA1[mi], fB1[ni][2 * pr], fB1[ni][2 * pr + 1]);
#pragma unroll
            for (int ni = 0; ni < 2; ni++)
                LDSM4(fB0[ni], st + O_B0 + boff[ni] + bq[ks]);
#pragma unroll
            for (int mi = 0; mi < 2; mi++)
#pragma unroll
                for (int ni = 0; ni < 2; ni++)
#pragma unroll
                    for (int pr = 0; pr < 2; pr++)
                        MMA_S8(cx[mi][ni][pr], fA1[mi], fB0[ni][2 * pr], fB0[ni][2 * pr + 1]);
#pragma unroll
            for (int mi = 0; mi < 2; mi++)
                LDSM4(fA0[mi], st + O_A0 + aoff[mi] + aq[ks]);
#pragma unroll
            for (int mi = 0; mi < 2; mi++)
#pragma unroll
                for (int ni = 0; ni < 2; ni++)
#pragma unroll
                    for (int pr = 0; pr < 2; pr++)
                        MMA_S8(cx[mi][ni][pr], fA0[mi], fB1[ni][2 * pr], fB1[ni][2 * pr + 1]);
        }
    }

#pragma unroll
    for (int mi = 0; mi < 2; mi++) {
#pragma unroll
        for (int ni = 0; ni < 2; ni++) {
#pragma unroll
            for (int pr = 0; pr < 2; pr++) {
                int col = bn + wn * 32 + ni * 16 + pr * 8 + 2 * t;
                float2 sb2 = *(const float2*)(sB + col);
                float2 bb = *(const float2*)(bias + col);
#pragma unroll
                for (int hf = 0; hf < 2; hf++) {
                    int r = bm + wm * 32 + mi * 16 + g + hf * 8;
                    float sa = sA[r];
                    float vx = sa * sb2.x * (16384.f * (float)hh[mi][ni][pr][2 * hf]
                              + 128.f * (float)cx[mi][ni][pr][2 * hf]) + bb.x;
                    float vy = sa * sb2.y * (16384.f * (float)hh[mi][ni][pr][2 * hf + 1]
                              + 128.f * (float)cx[mi][ni][pr][2 * hf + 1]) + bb.y;
                    if (act) { vx = gelu_f(vx); vy = gelu_f(vy); }
                    if (res) {
                        const float2 rr = *(const float2*)(res + (size_t)r * Nc + col);
                        vx += rr.x; vy += rr.y;
                    }
                    float2 o; o.x = vx; o.y = vy;
                    *(float2*)(Cf + (size_t)r * Nc + col) = o;
                }
            }
        }
    }
}

// ---------------------------------------------------------------------------
// int8 limb GEMM, 64x64 tile variant for wave-quantization-limited shapes
// (Wo, W2). 256 thr, 8 warps (4m x 2n), warp tile 16x32, BK=64, 4-stage,
// 16KB/stage -> 64KB smem, 2 CTAs/SM.
// ---------------------------------------------------------------------------
#define G64_A1 0
#define G64_A0 4096
#define G64_B1 8192
#define G64_B0 12288
#define G64_STG 16384
#define G64_SMEM (4 * G64_STG)   // 64KB

__global__ void __launch_bounds__(256, 2) s8_gemm64_kernel(
    const char* __restrict__ A1, const char* __restrict__ A0,
    const char* __restrict__ B1, const char* __restrict__ B0,
    const float* __restrict__ sA, const float* __restrict__ sB,
    const float* __restrict__ bias, const float* __restrict__ res,
    float* __restrict__ Cf, int Nc, int K, int act)
{
    extern __shared__ __align__(128) char smc[];
    const int tid = threadIdx.x;
    const int warp = tid >> 5, lane = tid & 31;
    const int wm = warp & 3, wn = warp >> 2;          // 4x2, warp tile 16x32
    const int g = lane >> 2, t = lane & 3;
    const int bm = blockIdx.y * 64, bn = blockIdx.x * 64;
    const int nk = K >> 6;

    uint32_t sbase;
    asm("{ .reg .u64 tt; cvta.to.shared.u64 tt, %1; cvt.u32.u64 %0, tt; }"
        : "=r"(sbase) : "l"(smc));

    const int arl = lane & 15, aqb = lane >> 4;
    const int arsw = (arl >> 1) & 3;
    const uint32_t aoff = (uint32_t)(wm * 16 + arl) * 64u;
    uint32_t aq[2];
#pragma unroll
    for (int ks = 0; ks < 2; ks++)
        aq[ks] = (uint32_t)(((2 * ks + aqb) ^ arsw) << 4);
    const int nrl = (lane & 7) + ((lane >> 4) << 3);
    const int bqb = (lane >> 3) & 1;
    const int brsw = (nrl >> 1) & 3;
    uint32_t boff[2], bq[2];
#pragma unroll
    for (int ni = 0; ni < 2; ni++)
        boff[ni] = (uint32_t)(wn * 32 + ni * 16 + nrl) * 64u;
#pragma unroll
    for (int ks = 0; ks < 2; ks++)
        bq[ks] = (uint32_t)(((2 * ks + bqb) ^ brsw) << 4);

    int hh[2][2][4], cx[2][2][4];
#pragma unroll
    for (int ni = 0; ni < 2; ni++)
#pragma unroll
        for (int pr = 0; pr < 2; pr++)
#pragma unroll
            for (int e = 0; e < 4; e++) { hh[ni][pr][e] = 0; cx[ni][pr][e] = 0; }

    auto load_stage = [&](int buf, int it) {
        if (it < nk) {
            uint32_t st = sbase + buf * G64_STG;
            int kb = it * 64;
            int m = tid >> 2, q = tid & 3;
            uint32_t woff = (uint32_t)(m * 64 + ((q ^ ((m >> 1) & 3)) << 4));
            size_t ga = (size_t)(bm + m) * K + kb + q * 16;
            cp16s(st + G64_A1 + woff, A1 + ga);
            cp16s(st + G64_A0 + woff, A0 + ga);
            size_t gb = (size_t)(bn + m) * K + kb + q * 16;
            cp16s(st + G64_B1 + woff, B1 + gb);
            cp16s(st + G64_B0 + woff, B0 + gb);
        }
        asm volatile("cp.async.commit_group;");
    };

    load_stage(0, 0);
    load_stage(1, 1);
    load_stage(2, 2);

    for (int it = 0; it < nk; it++) {
        asm volatile("cp.async.wait_group 2;");
        __syncthreads();
        load_stage((it + 3) & 3, it + 3);

        uint32_t st = sbase + (it & 3) * G64_STG;
#pragma unroll
        for (int ks = 0; ks < 2; ks++) {
            uint32_t fA1[4], fA0[4], fB1[2][4], fB0[2][4];
            LDSM4(fA1, st + G64_A1 + aoff + aq[ks]);
#pragma unroll
            for (int ni = 0; ni < 2; ni++)
                LDSM4(fB1[ni], st + G64_B1 + boff[ni] + bq[ks]);
#pragma unroll
            for (int ni = 0; ni < 2; ni++)
#pragma unroll
                for (int pr = 0; pr < 2; pr++)
                    MMA_S8(hh[ni][pr], fA1, fB1[ni][2 * pr], fB1[ni][2 * pr + 1]);
#pragma unroll
            for (int ni = 0; ni < 2; ni++)
                LDSM4(fB0[ni], st + G64_B0 + boff[ni] + bq[ks]);
#pragma unroll
            for (int ni = 0; ni < 2; ni++)
#pragma unroll
                for (int pr = 0; pr < 2; pr++)
                    MMA_S8(cx[ni][pr], fA1, fB0[ni][2 * pr], fB0[ni][2 * pr + 1]);
            LDSM4(fA0, st + G64_A0 + aoff + aq[ks]);
#pragma unroll
            for (int ni = 0; ni < 2; ni++)
#pragma unroll
                for (int pr = 0; pr < 2; pr++)
                    MMA_S8(cx[ni][pr], fA0, fB1[ni][2 * pr], fB1[ni][2 * pr + 1]);
        }
    }

#pragma unroll
    for (int ni = 0; ni < 2; ni++) {
#pragma unroll
        for (int pr = 0; pr < 2; pr++) {
            int col = bn + wn * 32 + ni * 16 + pr * 8 + 2 * t;
            float2 sb2 = *(const float2*)(sB + col);
            float2 bb = *(const float2*)(bias + col);
#pragma unroll
            for (int hf = 0; hf < 2; hf++) {
                int r = bm + wm * 16 + g + hf * 8;
                float sa = sA[r];
                float vx = sa * sb2.x * (16384.f * (float)hh[ni][pr][2 * hf]
                          + 128.f * (float)cx[ni][pr][2 * hf]) + bb.x;
                float vy = sa * sb2.y * (16384.f * (float)hh[ni][pr][2 * hf + 1]
                          + 128.f * (float)cx[ni][pr][2 * hf + 1]) + bb.y;
                if (act) { vx = gelu_f(vx); vy = gelu_f(vy); }
                if (res) {
                    const float2 rr = *(const float2*)(res + (size_t)r * Nc + col);
                    vx += rr.x; vy += rr.y;
                }
                float2 o; o.x = vx; o.y = vy;
                *(float2*)(Cf + (size_t)r * Nc + col) = o;
            }
        }
    }
}

// ---------------------------------------------------------------------------
// ffn row quant
__global__ void __launch_bounds__(256) ffn_quant_kernel(const float* __restrict__ f,
    char* __restrict__ o1, char* __restrict__ o0, float* __restrict__ sA)
{
    __shared__ float sb[9];
    int row = blockIdx.x, tid = threadIdx.x;
    int lane = tid & 31, w = tid >> 5;
    const float4* base = (const float4*)(f + (size_t)row * DFF);
    float mx = 0.f;
#pragma unroll
    for (int i = 0; i < 3; i++) {
        float4 v = base[tid + i * 256];
        mx = fmaxf(mx, fmaxf(fmaxf(fabsf(v.x), fabsf(v.y)), fmaxf(fabsf(v.z), fabsf(v.w))));
    }
#pragma unroll
    for (int o = 16; o; o >>= 1) mx = fmaxf(mx, __shfl_xor_sync(0xffffffffu, mx, o));
    if (lane == 0) sb[w] = mx;
    __syncthreads();
    if (w == 0) {
        float r = (lane < 8) ? sb[lane] : 0.f;
#pragma unroll
        for (int o = 4; o; o >>= 1) r = fmaxf(r, __shfl_xor_sync(0xffffffffu, r, o));
        if (lane == 0) sb[8] = r;
    }
    __syncthreads();
    float rmax = fmaxf(sb[8], 1e-20f);
    float inv = QMAX / rmax;
    uint32_t* p1 = (uint32_t*)(o1 + (size_t)row * DFF);
    uint32_t* p0 = (uint32_t*)(o0 + (size_t)row * DFF);
#pragma unroll
    for (int i = 0; i < 3; i++) {
        float4 v = base[tid + i * 256];
        char a1, a0, b1, b0, c1, c0, d1, d0;
        quant_limbs(v.x, inv, a1, a0);
        quant_limbs(v.y, inv, b1, b0);
        quant_limbs(v.z, inv, c1, c0);
        quant_limbs(v.w, inv, d1, d0);
        p1[tid + i * 256] = (uint32_t)(uint8_t)a1 | ((uint32_t)(uint8_t)b1 << 8)
                          | ((uint32_t)(uint8_t)c1 << 16) | ((uint32_t)(uint8_t)d1 << 24);
        p0[tid + i * 256] = (uint32_t)(uint8_t)a0 | ((uint32_t)(uint8_t)b0 << 8)
                          | ((uint32_t)(uint8_t)c0 << 16) | ((uint32_t)(uint8_t)d0 << 24);
    }
    if (tid == 0) sA[row] = rmax / QMAX;
}

// ---------------------------------------------------------------------------
// Poincare top-KNN: 2 rows/block, 256 threads, 32KB static smem.
// ---------------------------------------------------------------------------
__device__ __forceinline__ void ce64(unsigned long long& a, unsigned long long& b) {
    unsigned long long lo = min(a, b), hi = max(a, b);
    a = lo; b = hi;
}

__global__ void __launch_bounds__(256) topk2_kernel(const float* __restrict__ pos,
    const float* __restrict__ cptr, int* __restrict__ idxo, float* __restrict__ disto)
{
    __shared__ unsigned long long skv[2 * NTOK];      // 32 KB
    int tid = threadIdx.x;
    int base = blockIdx.x * 2;
    int b = base >> 11;
    float c = cptr[0];
    float inv_sqc = rsqrtf(c);
    const float* pb = pos + (size_t)b * NTOK * 2;

#pragma unroll
    for (int r2 = 0; r2 < 2; r2++) {
        int i = (base + r2) & (NTOK - 1);
        float yx = pb[i * 2], yy = pb[i * 2 + 1];
        float denY = 1.f - c * (yx * yx + yy * yy);
        unsigned long long k[8];
#pragma unroll
        for (int u = 0; u < 8; u++) {
            int j = tid + u * 256;
            float2 pj = *(const float2*)(pb + j * 2);
            float dx = pj.x - yx, dy = pj.y - yy;
            float num = 2.f * c * (dx * dx + dy * dy);
            float den = (1.f - c * (pj.x * pj.x + pj.y * pj.y)) * denY;
            float v = fmaxf(1.f + num / (den + 1e-8f), 1.f);
            k[u] = ((unsigned long long)__float_as_uint(v) << 32) | (unsigned)j;
        }
        ce64(k[0],k[1]); ce64(k[2],k[3]); ce64(k[4],k[5]); ce64(k[6],k[7]);
        ce64(k[0],k[2]); ce64(k[1],k[3]); ce64(k[4],k[6]); ce64(k[5],k[7]);
        ce64(k[1],k[2]); ce64(k[5],k[6]);
        ce64(k[0],k[4]); ce64(k[1],k[5]); ce64(k[2],k[6]); ce64(k[3],k[7]);
        ce64(k[2],k[4]); ce64(k[3],k[5]);
        ce64(k[1],k[2]); ce64(k[3],k[4]); ce64(k[5],k[6]);
#pragma unroll
        for (int u = 0; u < 8; u++) skv[r2 * NTOK + tid * 8 + u] = k[u];
    }
    __syncthreads();
    if (tid >= 64) return;                 // warps 2-7 retire

    int w = tid >> 5, lane = tid & 31;
    unsigned long long* rs = skv + w * NTOK;
    unsigned long long head[8];
    int ptr[8];
#pragma unroll
    for (int h = 0; h < 8; h++) { head[h] = rs[(lane * 8 + h) * 8]; ptr[h] = 0; }
    unsigned long long lmin = head[0]; int lh = 0;
#pragma unroll
    for (int h = 1; h < 8; h++)
        if (head[h] < lmin) { lmin = head[h]; lh = h; }

    unsigned long long mykey = 0xFFFFFFFFFFFFFFFFull;
    for (int sel = 0; sel < KNN; sel++) {
        unsigned long long bk = lmin; int bl = lane;
#pragma unroll
        for (int o = 16; o; o >>= 1) {
            unsigned long long ok = __shfl_xor_sync(0xffffffffu, bk, o);
            int ol = __shfl_xor_sync(0xffffffffu, bl, o);
            if (ok < bk) { bk = ok; bl = ol; }
        }
        if (lane == sel) mykey = bk;
        if (lane == bl) {
            int pp = ++ptr[lh];
            head[lh] = (pp < 8) ? rs[(lane * 8 + lh) * 8 + pp] : 0xFFFFFFFFFFFFFFFFull;
            lmin = head[0]; lh = 0;
#pragma unroll
            for (int h = 1; h < 8; h++)
                if (head[h] < lmin) { lmin = head[h]; lh = h; }
        }
    }
    int row = base + w;
    float v = __uint_as_float((unsigned)(mykey >> 32));
    idxo[(size_t)row * KNN + lane] = (int)(unsigned)(mykey & 0xFFFFFFFFull);
    disto[(size_t)row * KNN + lane] = acoshf(v) * inv_sqc;
}

// ---------------------------------------------------------------------------
// kNN attention: batched fp32 gather loads (MLP 16), int8-limb output + scale
__global__ void __launch_bounds__(384) attn_quant_kernel(const float* __restrict__ qkv,
    const int* __restrict__ idx, const float* __restrict__ dist,
    const float* __restrict__ log_tau,
    char* __restrict__ o1, char* __restrict__ o0, float* __restrict__ sA)
{
    __shared__ int sidx[KNN];
    __shared__ float sgeo[KNN];
    __shared__ float smax[13];
    int row = blockIdx.x;
    int lane = threadIdx.x & 31, h = threadIdx.x >> 5;
    float invtau = 1.f / (expf(log_tau[0]) + 1e-8f);
    if (threadIdx.x < KNN) {
        sidx[threadIdx.x] = idx[(size_t)row * KNN + threadIdx.x];
        sgeo[threadIdx.x] = -dist[(size_t)row * KNN + threadIdx.x] * invtau;
    }
    __syncthreads();
    int b = row >> 11;
    const float* qp = qkv + (size_t)row * 2304 + h * HDIM;
    float q0 = qp[2 * lane], q1 = qp[2 * lane + 1];
    const float* kb = qkv + (size_t)b * NTOK * 2304 + 768 + h * HDIM;
    const float* vb = qkv + (size_t)b * NTOK * 2304 + 1536 + h * HDIM;
    float myscore = 0.f;
#pragma unroll
    for (int j0 = 0; j0 < KNN; j0 += 8) {
        float ka[8], kc[8];
#pragma unroll
        for (int u = 0; u < 8; u++) {
            const float2 kv2 = *(const float2*)(kb + (size_t)sidx[j0 + u] * 2304 + 2 * lane);
            ka[u] = kv2.x; kc[u] = kv2.y;
        }
#pragma unroll
        for (int u = 0; u < 8; u++) {
            float p = q0 * ka[u] + q1 * kc[u];
#pragma unroll
            for (int o = 16; o; o >>= 1) p += __shfl_xor_sync(0xffffffffu, p, o);
            if (lane == j0 + u) myscore = p * 0.125f + sgeo[j0 + u];
        }
    }
    float m = myscore;
#pragma unroll
    for (int o = 16; o; o >>= 1) m = fmaxf(m, __shfl_xor_sync(0xffffffffu, m, o));
    float e = expf(myscore - m);
    float s = e;
#pragma unroll
    for (int o = 16; o; o >>= 1) s += __shfl_xor_sync(0xffffffffu, s, o);
    float p = e / s;
    float v0 = 0.f, v1 = 0.f;
#pragma unroll
    for (int j0 = 0; j0 < KNN; j0 += 8) {
        float va[8], vc[8];
#pragma unroll
        for (int u = 0; u < 8; u++) {
            const float2 vv2 = *(const float2*)(vb + (size_t)sidx[j0 + u] * 2304 + 2 * lane);
            va[u] = vv2.x; vc[u] = vv2.y;
        }
#pragma unroll
        for (int u = 0; u < 8; u++) {
            float pj = __shfl_sync(0xffffffffu, p, j0 + u);
            v0 += pj * va[u]; v1 += pj * vc[u];
        }
    }
    float mx = fmaxf(fabsf(v0), fabsf(v1));
#pragma unroll
    for (int o = 16; o; o >>= 1) mx = fmaxf(mx, __shfl_xor_sync(0xffffffffu, mx, o));
    if (lane == 0) smax[h] = mx;
    __syncthreads();
    if (h == 0) {
        float r = (lane < 12) ? smax[lane] : 0.f;
#pragma unroll
        for (int o = 16; o; o >>= 1) r = fmaxf(r, __shfl_xor_sync(0xffffffffu, r, o));
        if (lane == 0) smax[12] = r;
    }
    __syncthreads();
    float rmax = fmaxf(smax[12], 1e-20f);
    float inv = QMAX / rmax;
    char a1, a0, b1c, b0c;
    quant_limbs(v0, inv, a1, a0);
    quant_limbs(v1, inv, b1c, b0c);
    size_t oi = (size_t)row * DIMV + h * HDIM + 2 * lane;
    *(char2*)(o1 + oi) = make_char2(a1, b1c);
    *(char2*)(o0 + oi) = make_char2(a0, b0c);
    if (threadIdx.x == 0) sA[row] = rmax / QMAX;
}

// ---------------------------------------------------------------------------
extern "C" void kernel_launch(void* const* d_in, const int* in_sizes, int n_in,
                              void* d_out, int out_size)
{
    const float* x    = (const float*)d_in[0];
    const float* pos  = (const float*)d_in[1];
    const float* c    = (const float*)d_in[2];
    const float* temb = (const float*)d_in[3];
    const float* Wq = (const float*)d_in[4],  *bq = (const float*)d_in[5];
    const float* Wk = (const float*)d_in[6],  *bk = (const float*)d_in[7];
    const float* Wv = (const float*)d_in[8],  *bv = (const float*)d_in[9];
    const float* Wo = (const float*)d_in[10], *bo = (const float*)d_in[11];
    const float* W1 = (const float*)d_in[12], *b1 = (const float*)d_in[13];
    const float* W2 = (const float*)d_in[14], *b2 = (const float*)d_in[15];
    const float* g1 = (const float*)d_in[16], *be1 = (const float*)d_in[17];
    const float* g2 = (const float*)d_in[18], *be2 = (const float*)d_in[19];
    const float* log_tau = (const float*)d_in[20];
    float* out = (float*)d_out;

    char* arena; cudaGetSymbolAddress((void**)&arena, g_arena);
    int* idxp;   cudaGetSymbolAddress((void**)&idxp, g_idx);
    float* distp;cudaGetSymbolAddress((void**)&distp, g_dist);

    char* p = arena;
    auto carve = [&](size_t bytes) { char* r = p; p += (bytes + 127) & ~(size_t)127; return r; };
    char* h1   = carve((size_t)MROWS * 768);
    char* h0   = carve((size_t)MROWS * 768);
    char* att1 = carve((size_t)MROWS * 768);
    char* att0 = carve((size_t)MROWS * 768);
    char* h21  = carve((size_t)MROWS * 768);
    char* h20  = carve((size_t)MROWS * 768);
    char* ffn1 = carve((size_t)MROWS * 3072);
    char* ffn0 = carve((size_t)MROWS * 3072);
    char* wqkv1 = carve((size_t)2304 * 768);
    char* wqkv0 = carve((size_t)2304 * 768);
    char* wo1  = carve((size_t)768 * 768);
    char* wo0  = carve((size_t)768 * 768);
    char* w11  = carve((size_t)3072 * 768);
    char* w10  = carve((size_t)3072 * 768);
    char* w21  = carve((size_t)768 * 3072);
    char* w20  = carve((size_t)768 * 3072);
    float* qkv   = (float*)carve((size_t)MROWS * 2304 * 4);
    float* x2    = (float*)carve((size_t)MROWS * 768 * 4);
    float* ffn_f = (float*)carve((size_t)MROWS * 3072 * 4);
    float* partial = (float*)carve(8 * PSTRIDE * 4);
    float* sAh   = (float*)carve(MROWS * 4);
    float* sAatt = (float*)carve(MROWS * 4);
    float* sAh2  = (float*)carve(MROWS * 4);
    float* sAffn = (float*)carve(MROWS * 4);
    float* sBqkv = (float*)carve(2304 * 4);
    float* sBo   = (float*)carve(768 * 4);
    float* sB1   = (float*)carve(3072 * 4);
    float* sB2   = (float*)carve(768 * 4);
    float* bqkv  = (float*)carve(2304 * 4);

    cudaFuncSetAttribute(s8_gemm_kernel,
                         cudaFuncAttributeMaxDynamicSharedMemorySize, GEMM_SMEM);
    cudaFuncSetAttribute(s8_gemm64_kernel,
                         cudaFuncAttributeMaxDynamicSharedMemorySize, G64_SMEM);

    // launches 1-3, then topk2 as launch 4 (= ncu capture slot)
    ln_quant_kernel<<<MROWS, 384>>>(x, g1, be1, temb, h1, h0, sAh);
    wpmax_qkv_kernel<<<dim3(9, 8), 256>>>(Wq, Wk, Wv, bq, bk, bv, partial, bqkv);
    wquantT3_kernel<<<dim3(24, 24, 3), 256>>>(Wq, Wk, Wv, partial, sBqkv, wqkv1, wqkv0);
    topk2_kernel<<<MROWS / 2, 256>>>(pos, c, idxp, distp);

    s8_gemm_kernel<<<dim3(18, 32), 512, GEMM_SMEM>>>(h1, h0, wqkv1, wqkv0,
        sAh, sBqkv, bqkv, nullptr, qkv, 2304, 768, 0);
    attn_quant_kernel<<<MROWS, 384>>>(qkv, idxp, distp, log_tau, att1, att0, sAatt);

    wpmax_rest_kernel<<<dim3(18, 8), 256>>>(Wo, W1, W2, partial);
    wquantT_kernel<<<dim3(24, 24), 256>>>(Wo, partial, 2304, sBo, wo1, wo0, 768, 768);
    wquantT_kernel<<<dim3(96, 24), 256>>>(W1, partial, 3072, sB1, w11, w10, 3072, 768);
    wquantT_kernel<<<dim3(24, 96), 256>>>(W2, partial, 6144, sB2, w21, w20, 768, 3072);

    // x2 = x + att @ Wo  (64x64-tile variant: 768 blocks, no wave tail)
    s8_gemm64_kernel<<<dim3(12, 64), 256, G64_SMEM>>>(att1, att0, wo1, wo0,
        sAatt, sBo, bo, x, x2, 768, 768, 0);
    ln_quant_kernel<<<MROWS, 384>>>(x2, g2, be2, nullptr, h21, h20, sAh2);

    // ffn_f = gelu(h2 @ W1)
    s8_gemm_kernel<<<dim3(24, 32), 512, GEMM_SMEM>>>(h21, h20, w11, w10,
        sAh2, sB1, b1, nullptr, ffn_f, 3072, 768, 1);
    ffn_quant_kernel<<<MROWS, 256>>>(ffn_f, ffn1, ffn0, sAffn);

    // out = x2 + ffn @ W2  (64x64-tile variant: 768 blocks vs 192)
    s8_gemm64_kernel<<<dim3(12, 64), 256, G64_SMEM>>>(ffn1, ffn0, w21, w20,
        sAffn, sB2, b2, x2, out, 768, 3072, 0);
}